// round 12
// baseline (speedup 1.0000x reference)
#include <cuda_runtime.h>
#include <cuda_fp16.h>
#include <mma.h>
#include <cstdint>

using namespace nvcuda;

// Problem constants (GAE: GCN encoder x2 + inner-product decoder)
#define NN 50000
#define NE 1600000
#define IN_CH 256
#define HID 256
#define OUT_CH 128
#define GK 256   // K dim of both GEMMs

// ---------------- scratch (static device globals; no allocation) ----------
__device__ __align__(256) int    g_cnt[NN];
__device__ __align__(256) int    g_rowstart[NN + 1];
__device__ __align__(256) int    g_pos[NN];
__device__ __align__(256) float  g_dinv[NN];
__device__ __align__(256) int    g_csr[NE];
__device__ __align__(256) int    g_eid[NE];                   // original edge id per CSR slot
__device__ __align__(256) __half g_xh[(size_t)NN * IN_CH];    // fp16 x (unscaled)
__device__ __align__(256) __half g_w1h[GK * HID];             // fp16 W1
__device__ __align__(256) __half g_w2h[GK * OUT_CH];          // fp16 W2
__device__ __align__(256) __half g_h1h[(size_t)NN * HID];     // fp16: x@W1, then *= dinv[row]
__device__ __align__(256) __half g_z1h[(size_t)NN * HID];     // fp16: relu(agg*di+b1)*di
__device__ __align__(256) __half g_h2h[(size_t)NN * OUT_CH];  // fp16: z1h@W2 (rows pre-scaled)
__device__ __align__(256) __half g_z2h[(size_t)NN * OUT_CH];  // fp16: agg*di+b2

// ---------------- degree / CSR build --------------------------------------
__global__ void k_zero_cnt(int n) {
    int i = blockIdx.x * blockDim.x + threadIdx.x;
    if (i < n) g_cnt[i] = 0;
}

__global__ void k_count(const int* __restrict__ ei, int E, int n) {
    int e = blockIdx.x * blockDim.x + threadIdx.x;
    if (e < E) {
        int d = ei[(size_t)E + e];
        if ((unsigned)d < (unsigned)n) atomicAdd(&g_cnt[d], 1);
    }
}

__global__ void k_scan(int n) {
    __shared__ int part[1024];
    int t = threadIdx.x;
    const int CHUNK = (NN + 1023) / 1024;
    int lo = t * CHUNK;
    int hi = lo + CHUNK; if (hi > n) hi = n;
    int s = 0;
    for (int i = lo; i < hi; i++) s += g_cnt[i];
    part[t] = s;
    __syncthreads();
    for (int off = 1; off < 1024; off <<= 1) {
        int v = (t >= off) ? part[t - off] : 0;
        __syncthreads();
        part[t] += v;
        __syncthreads();
    }
    int base = (t == 0) ? 0 : part[t - 1];
    for (int i = lo; i < hi; i++) {
        g_rowstart[i] = base;
        g_pos[i] = base;
        g_dinv[i] = rsqrtf((float)(g_cnt[i] + 1));
        base += g_cnt[i];
    }
    if (t == 0) g_rowstart[n] = part[1023];
}

__global__ void k_fill(const int* __restrict__ ei, int E, int n) {
    int e = blockIdx.x * blockDim.x + threadIdx.x;
    if (e < E) {
        int s = ei[e];
        int d = ei[(size_t)E + e];
        if ((unsigned)s < (unsigned)n && (unsigned)d < (unsigned)n) {
            int p = atomicAdd(&g_pos[d], 1);
            if ((unsigned)p < (unsigned)NE) {
                g_csr[p] = s;
                g_eid[p] = e;
            }
        }
    }
}

// ---------------- conversions (no dinv dependency -> overlappable) --------
__device__ __forceinline__ void cvt_chunk(const float* __restrict__ S,
                                          __half* __restrict__ D, int i) {
    float4 v = __ldg((const float4*)S + i);
    __half2 lo = __floats2half2_rn(v.x, v.y);
    __half2 hi = __floats2half2_rn(v.z, v.w);
    uint2 o; o.x = *(unsigned*)&lo; o.y = *(unsigned*)&hi;
    *((uint2*)D + i) = o;
}

__global__ void k_cvt_x(const float* __restrict__ x, int n) {
    int i = blockIdx.x * blockDim.x + threadIdx.x;
    if (i < n * (IN_CH / 4)) cvt_chunk(x, g_xh, i);
}

__global__ void k_cvt_w(const float* __restrict__ W1, const float* __restrict__ W2) {
    int i = blockIdx.x * blockDim.x + threadIdx.x;
    const int C1 = GK * HID / 4;
    const int C2 = GK * OUT_CH / 4;
    if (i < C1) cvt_chunk(W1, g_w1h, i);
    else if (i < C1 + C2) cvt_chunk(W2, g_w2h, i - C1);
}

// post-join: h1h[row,:] *= dinv[row]
__global__ void k_scale_h1(int n) {
    int i = blockIdx.x * blockDim.x + threadIdx.x;   // one uint4 (8 halves)
    int total = n * (HID / 8);
    if (i >= total) return;
    float di = g_dinv[i / (HID / 8)];
    uint4 v = *((const uint4*)g_h1h + i);
    __half2* p = (__half2*)&v;
#pragma unroll
    for (int j = 0; j < 4; j++) {
        float2 f = __half22float2(p[j]);
        p[j] = __floats2half2_rn(f.x * di, f.y * di);
    }
    *((uint4*)g_h1h + i) = v;
}

// ---------------- wmma fp16 GEMM: C = A[M,256] @ B[256,Ncols] --------------
#define BM 128
#define BN 64
#define BK 32
#define A_LD 40   // BK + 8 pad (halves)
#define B_LD 72   // BN + 8 pad (halves)
#define C_LD 68   // BN + 4 pad (floats)

__device__ __forceinline__ void gemm_wmma_body(
    const __half* __restrict__ A, const __half* __restrict__ B,
    __half* __restrict__ C, int rowBase, int M, int Ncols)
{
    __shared__ __align__(16) char sm[BM * C_LD * 4];   // 34816 B; unioned A/B vs C
    __half* As = (__half*)sm;                          // [BM][A_LD]
    __half* Bs = As + BM * A_LD;                       // [BK][B_LD]
    float*  Cs = (float*)sm;                           // [BM][C_LD]

    int tid = threadIdx.x;
    int warp = tid >> 5;
    int wrow = warp >> 1;
    int wcol = warp & 1;
    int row0 = rowBase + blockIdx.y * BM;
    int col0 = blockIdx.x * BN;

    wmma::fragment<wmma::accumulator, 16, 16, 16, float> c[2][2];
#pragma unroll
    for (int i = 0; i < 2; i++)
#pragma unroll
        for (int j = 0; j < 2; j++) wmma::fill_fragment(c[i][j], 0.f);

    for (int k0 = 0; k0 < GK; k0 += BK) {
#pragma unroll
        for (int t = 0; t < 2; t++) {
            int v = tid + t * 256;
            int r = v >> 2;
            int kc = (v & 3) * 8;
            int grow = row0 + r;
            uint4 val = make_uint4(0u, 0u, 0u, 0u);
            if (grow < M)
                val = *(const uint4*)(A + (size_t)grow * GK + k0 + kc);
            *(uint4*)(As + r * A_LD + kc) = val;
        }
        {
            int r = tid >> 3;
            int c8 = (tid & 7) * 8;
            uint4 val = *(const uint4*)(B + (size_t)(k0 + r) * Ncols + col0 + c8);
            *(uint4*)(Bs + r * B_LD + c8) = val;
        }
        __syncthreads();

#pragma unroll
        for (int kk = 0; kk < BK; kk += 16) {
            wmma::fragment<wmma::matrix_a, 16, 16, 16, __half, wmma::row_major> a[2];
            wmma::fragment<wmma::matrix_b, 16, 16, 16, __half, wmma::row_major> b[2];
#pragma unroll
            for (int i = 0; i < 2; i++)
                wmma::load_matrix_sync(a[i], As + (wrow * 32 + i * 16) * A_LD + kk, A_LD);
#pragma unroll
            for (int j = 0; j < 2; j++)
                wmma::load_matrix_sync(b[j], Bs + kk * B_LD + wcol * 32 + j * 16, B_LD);
#pragma unroll
            for (int i = 0; i < 2; i++)
#pragma unroll
                for (int j = 0; j < 2; j++)
                    wmma::mma_sync(c[i][j], a[i], b[j], c[i][j]);
        }
        __syncthreads();
    }

#pragma unroll
    for (int i = 0; i < 2; i++)
#pragma unroll
        for (int j = 0; j < 2; j++)
            wmma::store_matrix_sync(Cs + (wrow * 32 + i * 16) * C_LD + wcol * 32 + j * 16,
                                    c[i][j], C_LD, wmma::mem_row_major);
    __syncthreads();

    if (tid < BM) {
        int grow = row0 + tid;
        if (grow < M) {
            const float* src = Cs + tid * C_LD;
            __half* dst = C + (size_t)grow * Ncols + col0;
#pragma unroll
            for (int cB = 0; cB < BN; cB += 8) {
                __half2 p0 = __floats2half2_rn(src[cB + 0], src[cB + 1]);
                __half2 p1 = __floats2half2_rn(src[cB + 2], src[cB + 3]);
                __half2 p2 = __floats2half2_rn(src[cB + 4], src[cB + 5]);
                __half2 p3 = __floats2half2_rn(src[cB + 6], src[cB + 7]);
                uint4 o;
                o.x = *(unsigned*)&p0; o.y = *(unsigned*)&p1;
                o.z = *(unsigned*)&p2; o.w = *(unsigned*)&p3;
                *(uint4*)(dst + cB) = o;
            }
        }
    }
}

__global__ __launch_bounds__(256) void k_gemm1(int M) {
    gemm_wmma_body(g_xh, g_w1h, g_h1h, 0, M, HID);
}

__global__ __launch_bounds__(256) void k_gemm2(int rowBase, int M) {
    gemm_wmma_body(g_z1h, g_w2h, g_h2h, rowBase, M, OUT_CH);
}

// ---------------- CSR aggregation (pure row-sum; rows pre-scaled) ----------
__device__ __forceinline__ void acc8_add(float* acc, uint4 v) {
    const __half2* p = (const __half2*)&v;
#pragma unroll
    for (int j = 0; j < 4; j++) {
        float2 f = __half22float2(p[j]);
        acc[2 * j]     += f.x;
        acc[2 * j + 1] += f.y;
    }
}

// agg1 over node range [base, limit): one warp/node.
__global__ __launch_bounds__(256) void k_agg1(const float* __restrict__ bias,
                                              int base, int limit)
{
    int node = base + ((blockIdx.x * blockDim.x + threadIdx.x) >> 5);
    if (node >= limit) return;
    int lane = threadIdx.x & 31;
    const unsigned FULL = 0xffffffffu;

    float acc[8] = {0.f, 0.f, 0.f, 0.f, 0.f, 0.f, 0.f, 0.f};
    acc8_add(acc, __ldg((const uint4*)(g_h1h + (size_t)node * HID) + lane));

    int beg = g_rowstart[node];
    int end = g_rowstart[node + 1];
    for (int i0 = beg; i0 < end; i0 += 32) {
        int cnt = end - i0; if (cnt > 32) cnt = 32;
        int myidx = (i0 + lane < end) ? g_csr[i0 + lane] : 0;
        int j = 0;
        for (; j + 8 <= cnt; j += 8) {
            int nb[8];
#pragma unroll
            for (int u = 0; u < 8; u++) nb[u] = __shfl_sync(FULL, myidx, j + u);
            uint4 v[8];
#pragma unroll
            for (int u = 0; u < 8; u++)
                v[u] = __ldg((const uint4*)(g_h1h + (size_t)nb[u] * HID) + lane);
#pragma unroll
            for (int u = 0; u < 8; u++) acc8_add(acc, v[u]);
        }
        for (; j < cnt; j++) {
            int nb = __shfl_sync(FULL, myidx, j);
            acc8_add(acc, __ldg((const uint4*)(g_h1h + (size_t)nb * HID) + lane));
        }
    }

    float di = g_dinv[node];
    float4 b0 = __ldg((const float4*)bias + lane * 2);
    float4 b1v = __ldg((const float4*)bias + lane * 2 + 1);
    float o[8];
    o[0] = fmaxf(acc[0] * di + b0.x, 0.f) * di;
    o[1] = fmaxf(acc[1] * di + b0.y, 0.f) * di;
    o[2] = fmaxf(acc[2] * di + b0.z, 0.f) * di;
    o[3] = fmaxf(acc[3] * di + b0.w, 0.f) * di;
    o[4] = fmaxf(acc[4] * di + b1v.x, 0.f) * di;
    o[5] = fmaxf(acc[5] * di + b1v.y, 0.f) * di;
    o[6] = fmaxf(acc[6] * di + b1v.z, 0.f) * di;
    o[7] = fmaxf(acc[7] * di + b1v.w, 0.f) * di;
    __half2 h0 = __floats2half2_rn(o[0], o[1]);
    __half2 h1 = __floats2half2_rn(o[2], o[3]);
    __half2 h2 = __floats2half2_rn(o[4], o[5]);
    __half2 h3 = __floats2half2_rn(o[6], o[7]);
    uint4 ov;
    ov.x = *(unsigned*)&h0; ov.y = *(unsigned*)&h1;
    ov.z = *(unsigned*)&h2; ov.w = *(unsigned*)&h3;
    *((uint4*)(g_z1h + (size_t)node * HID) + lane) = ov;
}

// agg2: one node per 16-lane group; group-local shfl.
__global__ __launch_bounds__(256) void k_agg2(const float* __restrict__ bias, int n)
{
    int node = (blockIdx.x * blockDim.x + threadIdx.x) >> 4;
    if (node >= n) return;
    int lane = threadIdx.x & 31;
    int grp  = lane >> 4;
    int l16  = lane & 15;
    unsigned GM = 0xFFFFu << (grp * 16);

    float acc[8] = {0.f, 0.f, 0.f, 0.f, 0.f, 0.f, 0.f, 0.f};
    acc8_add(acc, __ldg((const uint4*)(g_h2h + (size_t)node * OUT_CH) + l16));

    int beg = g_rowstart[node];
    int end = g_rowstart[node + 1];
    for (int i0 = beg; i0 < end; i0 += 16) {
        int cnt = end - i0; if (cnt > 16) cnt = 16;
        int myidx = (i0 + l16 < end) ? g_csr[i0 + l16] : 0;
        int j = 0;
        for (; j + 8 <= cnt; j += 8) {
            int nb[8];
#pragma unroll
            for (int u = 0; u < 8; u++) nb[u] = __shfl_sync(GM, myidx, j + u, 16);
            uint4 v[8];
#pragma unroll
            for (int u = 0; u < 8; u++)
                v[u] = __ldg((const uint4*)(g_h2h + (size_t)nb[u] * OUT_CH) + l16);
#pragma unroll
            for (int u = 0; u < 8; u++) acc8_add(acc, v[u]);
        }
        for (; j < cnt; j++) {
            int nb = __shfl_sync(GM, myidx, j, 16);
            acc8_add(acc, __ldg((const uint4*)(g_h2h + (size_t)nb * OUT_CH) + l16));
        }
    }

    float di = g_dinv[node];
    float4 b0 = __ldg((const float4*)bias + l16 * 2);
    float4 b1v = __ldg((const float4*)bias + l16 * 2 + 1);
    __half2 h0 = __floats2half2_rn(acc[0] * di + b0.x,  acc[1] * di + b0.y);
    __half2 h1 = __floats2half2_rn(acc[2] * di + b0.z,  acc[3] * di + b0.w);
    __half2 h2 = __floats2half2_rn(acc[4] * di + b1v.x, acc[5] * di + b1v.y);
    __half2 h3 = __floats2half2_rn(acc[6] * di + b1v.z, acc[7] * di + b1v.w);
    uint4 ov;
    ov.x = *(unsigned*)&h0; ov.y = *(unsigned*)&h1;
    ov.z = *(unsigned*)&h2; ov.w = *(unsigned*)&h3;
    *((uint4*)(g_z2h + (size_t)node * OUT_CH) + l16) = ov;
}

// ---------------- decoder (CSR order): dst row cached in registers ---------
// One 16-lane group per dst node. Load z2[dst] once; per incident edge load
// z2[src], dot, scatter to out[eid] (original edge order).
__global__ __launch_bounds__(256) void k_decode_csr(float* __restrict__ out, int n)
{
    int node = (blockIdx.x * blockDim.x + threadIdx.x) >> 4;
    if (node >= n) return;
    int lane = threadIdx.x & 31;
    int grp  = lane >> 4;
    int l16  = lane & 15;
    unsigned GM = 0xFFFFu << (grp * 16);

    // cache this dst's z2 row as 8 floats per lane
    float dreg[8];
    {
        uint4 v = __ldg((const uint4*)(g_z2h + (size_t)node * OUT_CH) + l16);
        const __half2* p = (const __half2*)&v;
#pragma unroll
        for (int j = 0; j < 4; j++) {
            float2 f = __half22float2(p[j]);
            dreg[2 * j] = f.x; dreg[2 * j + 1] = f.y;
        }
    }

    int beg = g_rowstart[node];
    int end = g_rowstart[node + 1];
    for (int i0 = beg; i0 < end; i0 += 16) {
        int cnt = end - i0; if (cnt > 16) cnt = 16;
        int my_s  = (i0 + l16 < end) ? g_csr[i0 + l16] : 0;
        int my_e  = (i0 + l16 < end) ? g_eid[i0 + l16] : 0;
        int j = 0;
        for (; j + 4 <= cnt; j += 4) {
            int s[4], eid[4];
#pragma unroll
            for (int u = 0; u < 4; u++) {
                s[u]   = __shfl_sync(GM, my_s, j + u, 16);
                eid[u] = __shfl_sync(GM, my_e, j + u, 16);
            }
            uint4 v[4];
#pragma unroll
            for (int u = 0; u < 4; u++)
                v[u] = __ldg((const uint4*)(g_z2h + (size_t)s[u] * OUT_CH) + l16);
            float p[4];
#pragma unroll
            for (int u = 0; u < 4; u++) {
                const __half2* ph = (const __half2*)&v[u];
                float acc = 0.f;
#pragma unroll
                for (int jj = 0; jj < 4; jj++) {
                    float2 f = __half22float2(ph[jj]);
                    acc += dreg[2 * jj] * f.x + dreg[2 * jj + 1] * f.y;
                }
                p[u] = acc;
            }
#pragma unroll
            for (int off = 8; off > 0; off >>= 1) {
#pragma unroll
                for (int u = 0; u < 4; u++)
                    p[u] += __shfl_down_sync(GM, p[u], off, 16);
            }
            if (l16 == 0) {
#pragma unroll
                for (int u = 0; u < 4; u++) out[eid[u]] = p[u];
            }
        }
        for (; j < cnt; j++) {
            int s   = __shfl_sync(GM, my_s, j, 16);
            int eid = __shfl_sync(GM, my_e, j, 16);
            uint4 v = __ldg((const uint4*)(g_z2h + (size_t)s * OUT_CH) + l16);
            const __half2* ph = (const __half2*)&v;
            float acc = 0.f;
#pragma unroll
            for (int jj = 0; jj < 4; jj++) {
                float2 f = __half22float2(ph[jj]);
                acc += dreg[2 * jj] * f.x + dreg[2 * jj + 1] * f.y;
            }
#pragma unroll
            for (int off = 8; off > 0; off >>= 1)
                acc += __shfl_down_sync(GM, acc, off, 16);
            if (l16 == 0) out[eid] = acc;
        }
    }
}

// ---------------- launch ---------------------------------------------------
extern "C" void kernel_launch(void* const* d_in, const int* in_sizes, int n_in,
                              void* d_out, int out_size)
{
    const float* x  = (const float*)d_in[0];
    const int*   ei = (const int*)d_in[1];   // [2, E] indices, staged as int32
    const float* W1 = (const float*)d_in[2];
    const float* b1 = (const float*)d_in[3];
    const float* W2 = (const float*)d_in[4];
    const float* b2 = (const float*)d_in[5];
    float* out = (float*)d_out;

    int n = in_sizes[0] / IN_CH;    // 50000
    int E = in_sizes[1] / 2;        // 1600000
    int nh = ((n / 2 + BM - 1) / BM) * BM;   // chunk split, BM-aligned
    if (nh > n) nh = n;

    // Streams/events: capture-legal fork/join; runs only at capture time.
    cudaStream_t s2;
    cudaStreamCreate(&s2);
    cudaEvent_t evFork, evJoin, evA, evG2a;
    cudaEventCreateWithFlags(&evFork, cudaEventDisableTiming);
    cudaEventCreateWithFlags(&evJoin, cudaEventDisableTiming);
    cudaEventCreateWithFlags(&evA, cudaEventDisableTiming);
    cudaEventCreateWithFlags(&evG2a, cudaEventDisableTiming);

    cudaEventRecord(evFork, 0);
    cudaStreamWaitEvent(s2, evFork, 0);

    // Branch A (default stream): CSR build (atomics / ALU bound)
    k_zero_cnt<<<(n + 255) / 256, 256>>>(n);
    k_count<<<(E + 255) / 256, 256>>>(ei, E, n);
    k_scan<<<1, 1024>>>(n);
    k_fill<<<(E + 255) / 256, 256>>>(ei, E, n);

    // Branch B (s2): fp16 conversions + GEMM1 (tensor / L2 bound)
    k_cvt_x<<<(n * (IN_CH / 4) + 255) / 256, 256, 0, s2>>>(x, n);
    k_cvt_w<<<((GK * HID + GK * OUT_CH) / 4 + 255) / 256, 256, 0, s2>>>(W1, W2);
    {
        dim3 grid(HID / BN, (n + BM - 1) / BM);
        k_gemm1<<<grid, 256, 0, s2>>>(n);
    }
    cudaEventRecord(evJoin, s2);
    cudaStreamWaitEvent(0, evJoin, 0);

    // Joined: scale h1 rows, then pipelined agg1 / gemm2 over two node chunks
    k_scale_h1<<<(n * (HID / 8) + 255) / 256, 256>>>(n);

    k_agg1<<<(nh * 32 + 255) / 256, 256>>>(b1, 0, nh);           // chunk 0
    cudaEventRecord(evA, 0);

    cudaStreamWaitEvent(s2, evA, 0);                             // gemm2 chunk 0 || agg1 chunk 1
    {
        dim3 grid(OUT_CH / BN, nh / BM);
        k_gemm2<<<grid, 256, 0, s2>>>(0, n);
    }
    cudaEventRecord(evG2a, s2);

    k_agg1<<<((n - nh) * 32 + 255) / 256, 256>>>(b1, nh, n);     // chunk 1
    {
        dim3 grid(OUT_CH / BN, (n - nh + BM - 1) / BM);
        k_gemm2<<<grid, 256>>>(nh, n);
    }
    cudaStreamWaitEvent(0, evG2a, 0);

    // agg2 (node per 16-lane group) and decode over CSR (dst row cached)
    k_agg2<<<(n * 16 + 255) / 256, 256>>>(b2, n);
    k_decode_csr<<<(n * 16 + 255) / 256, 256>>>(out, n);

    cudaEventDestroy(evFork);
    cudaEventDestroy(evJoin);
    cudaEventDestroy(evA);
    cudaEventDestroy(evG2a);
    cudaStreamDestroy(s2);
}

// round 13
// speedup vs baseline: 1.2617x; 1.2617x over previous
#include <cuda_runtime.h>
#include <cuda_fp16.h>
#include <mma.h>
#include <cstdint>

using namespace nvcuda;

// Problem constants (GAE: GCN encoder x2 + inner-product decoder)
#define NN 50000
#define NE 1600000
#define IN_CH 256
#define HID 256
#define OUT_CH 128
#define GK 256   // K dim of both GEMMs

// ---------------- scratch (static device globals; no allocation) ----------
__device__ __align__(256) int    g_cnt[NN];
__device__ __align__(256) int    g_rowstart[NN + 1];
__device__ __align__(256) int    g_pos[NN];
__device__ __align__(256) float  g_dinv[NN];
__device__ __align__(256) int    g_csr[NE];
__device__ __align__(256) int    g_blksum[256];
__device__ __align__(256) int    g_blkoff[256];
__device__ __align__(256) __half g_xh[(size_t)NN * IN_CH];    // fp16 x (unscaled)
__device__ __align__(256) __half g_w1h[GK * HID];             // fp16 W1
__device__ __align__(256) __half g_w2h[GK * OUT_CH];          // fp16 W2
__device__ __align__(256) __half g_h1h[(size_t)NN * HID];     // fp16: x@W1, then *= dinv[row]
__device__ __align__(256) __half g_z1h[(size_t)NN * HID];     // fp16: relu(agg*di+b1)*di
__device__ __align__(256) __half g_h2h[(size_t)NN * OUT_CH];  // fp16: z1h@W2 (rows pre-scaled)
__device__ __align__(256) __half g_z2h[(size_t)NN * OUT_CH];  // fp16: agg*di+b2

// ---------------- degree / CSR build --------------------------------------
// edge_index staged as int32, layout [2,E]: src=ei[e], dst=ei[E+e].
__global__ void k_zero_cnt(int n) {
    int i = blockIdx.x * blockDim.x + threadIdx.x;
    if (i < n) g_cnt[i] = 0;
}

// 4 edges per thread via int4 (E is a multiple of 4)
__global__ void k_count4(const int* __restrict__ ei, int E, int n) {
    int i = blockIdx.x * blockDim.x + threadIdx.x;
    if (i < E / 4) {
        int4 d = __ldg((const int4*)(ei + E) + i);
        if ((unsigned)d.x < (unsigned)n) atomicAdd(&g_cnt[d.x], 1);
        if ((unsigned)d.y < (unsigned)n) atomicAdd(&g_cnt[d.y], 1);
        if ((unsigned)d.z < (unsigned)n) atomicAdd(&g_cnt[d.z], 1);
        if ((unsigned)d.w < (unsigned)n) atomicAdd(&g_cnt[d.w], 1);
    }
}

// multi-block exclusive scan: scan1 (block sums) -> scan2 (scan sums) -> scan3
__global__ void k_scan1(int n) {
    int t = threadIdx.x;
    int i = blockIdx.x * 256 + t;
    int v = (i < n) ? g_cnt[i] : 0;
    __shared__ int sm[256];
    sm[t] = v;
    __syncthreads();
    for (int off = 1; off < 256; off <<= 1) {
        int u = (t >= off) ? sm[t - off] : 0;
        __syncthreads();
        sm[t] += u;
        __syncthreads();
    }
    if (t == 255) g_blksum[blockIdx.x] = sm[255];
}

__global__ void k_scan2(int nb, int n) {
    int t = threadIdx.x;
    int v = (t < nb) ? g_blksum[t] : 0;
    __shared__ int sm[256];
    sm[t] = v;
    __syncthreads();
    for (int off = 1; off < 256; off <<= 1) {
        int u = (t >= off) ? sm[t - off] : 0;
        __syncthreads();
        sm[t] += u;
        __syncthreads();
    }
    if (t < nb) g_blkoff[t] = sm[t] - v;   // exclusive
    if (t == 255) g_rowstart[n] = sm[255]; // total
}

__global__ void k_scan3(int n) {
    int t = threadIdx.x;
    int i = blockIdx.x * 256 + t;
    int v = (i < n) ? g_cnt[i] : 0;
    __shared__ int sm[256];
    sm[t] = v;
    __syncthreads();
    for (int off = 1; off < 256; off <<= 1) {
        int u = (t >= off) ? sm[t - off] : 0;
        __syncthreads();
        sm[t] += u;
        __syncthreads();
    }
    if (i < n) {
        int excl = sm[t] - v + g_blkoff[blockIdx.x];
        g_rowstart[i] = excl;
        g_pos[i] = excl;
        g_dinv[i] = rsqrtf((float)(v + 1));
    }
}

// 4 edges per thread
__global__ void k_fill4(const int* __restrict__ ei, int E, int n) {
    int i = blockIdx.x * blockDim.x + threadIdx.x;
    if (i < E / 4) {
        int4 s4 = __ldg((const int4*)ei + i);
        int4 d4 = __ldg((const int4*)(ei + E) + i);
        int ss[4] = {s4.x, s4.y, s4.z, s4.w};
        int dd[4] = {d4.x, d4.y, d4.z, d4.w};
#pragma unroll
        for (int u = 0; u < 4; u++) {
            if ((unsigned)ss[u] < (unsigned)n && (unsigned)dd[u] < (unsigned)n) {
                int p = atomicAdd(&g_pos[dd[u]], 1);
                if ((unsigned)p < (unsigned)NE) g_csr[p] = ss[u];
            }
        }
    }
}

// ---------------- conversions ----------------------------------------------
__device__ __forceinline__ void cvt_chunk(const float* __restrict__ S,
                                          __half* __restrict__ D, int i) {
    float4 v = __ldg((const float4*)S + i);
    __half2 lo = __floats2half2_rn(v.x, v.y);
    __half2 hi = __floats2half2_rn(v.z, v.w);
    uint2 o; o.x = *(unsigned*)&lo; o.y = *(unsigned*)&hi;
    *((uint2*)D + i) = o;
}

// converts float4-chunks [lo4, hi4) of x
__global__ void k_cvt_x(const float* __restrict__ x, int lo4, int hi4) {
    int i = lo4 + blockIdx.x * blockDim.x + threadIdx.x;
    if (i < hi4) cvt_chunk(x, g_xh, i);
}

__global__ void k_cvt_w(const float* __restrict__ W1, const float* __restrict__ W2) {
    int i = blockIdx.x * blockDim.x + threadIdx.x;
    const int C1 = GK * HID / 4;
    const int C2 = GK * OUT_CH / 4;
    if (i < C1) cvt_chunk(W1, g_w1h, i);
    else if (i < C1 + C2) cvt_chunk(W2, g_w2h, i - C1);
}

// post-join: h1h[row,:] *= dinv[row]
__global__ void k_scale_h1(int n) {
    int i = blockIdx.x * blockDim.x + threadIdx.x;   // one uint4 (8 halves)
    int total = n * (HID / 8);
    if (i >= total) return;
    float di = g_dinv[i / (HID / 8)];
    uint4 v = *((const uint4*)g_h1h + i);
    __half2* p = (__half2*)&v;
#pragma unroll
    for (int j = 0; j < 4; j++) {
        float2 f = __half22float2(p[j]);
        p[j] = __floats2half2_rn(f.x * di, f.y * di);
    }
    *((uint4*)g_h1h + i) = v;
}

// ---------------- wmma fp16 GEMM: C = A[M,256] @ B[256,Ncols] --------------
#define BM 128
#define BN 64
#define BK 32
#define A_LD 40   // BK + 8 pad (halves)
#define B_LD 72   // BN + 8 pad (halves)
#define C_LD 68   // BN + 4 pad (floats)

__device__ __forceinline__ void gemm_wmma_body(
    const __half* __restrict__ A, const __half* __restrict__ B,
    __half* __restrict__ C, int rowBase, int M, int Ncols)
{
    __shared__ __align__(16) char sm[BM * C_LD * 4];   // 34816 B; unioned A/B vs C
    __half* As = (__half*)sm;                          // [BM][A_LD]
    __half* Bs = As + BM * A_LD;                       // [BK][B_LD]
    float*  Cs = (float*)sm;                           // [BM][C_LD]

    int tid = threadIdx.x;
    int warp = tid >> 5;
    int wrow = warp >> 1;
    int wcol = warp & 1;
    int row0 = rowBase + blockIdx.y * BM;
    int col0 = blockIdx.x * BN;

    wmma::fragment<wmma::accumulator, 16, 16, 16, float> c[2][2];
#pragma unroll
    for (int i = 0; i < 2; i++)
#pragma unroll
        for (int j = 0; j < 2; j++) wmma::fill_fragment(c[i][j], 0.f);

    for (int k0 = 0; k0 < GK; k0 += BK) {
#pragma unroll
        for (int t = 0; t < 2; t++) {
            int v = tid + t * 256;
            int r = v >> 2;
            int kc = (v & 3) * 8;
            int grow = row0 + r;
            uint4 val = make_uint4(0u, 0u, 0u, 0u);
            if (grow < M)
                val = *(const uint4*)(A + (size_t)grow * GK + k0 + kc);
            *(uint4*)(As + r * A_LD + kc) = val;
        }
        {
            int r = tid >> 3;
            int c8 = (tid & 7) * 8;
            uint4 val = *(const uint4*)(B + (size_t)(k0 + r) * Ncols + col0 + c8);
            *(uint4*)(Bs + r * B_LD + c8) = val;
        }
        __syncthreads();

#pragma unroll
        for (int kk = 0; kk < BK; kk += 16) {
            wmma::fragment<wmma::matrix_a, 16, 16, 16, __half, wmma::row_major> a[2];
            wmma::fragment<wmma::matrix_b, 16, 16, 16, __half, wmma::row_major> b[2];
#pragma unroll
            for (int i = 0; i < 2; i++)
                wmma::load_matrix_sync(a[i], As + (wrow * 32 + i * 16) * A_LD + kk, A_LD);
#pragma unroll
            for (int j = 0; j < 2; j++)
                wmma::load_matrix_sync(b[j], Bs + kk * B_LD + wcol * 32 + j * 16, B_LD);
#pragma unroll
            for (int i = 0; i < 2; i++)
#pragma unroll
                for (int j = 0; j < 2; j++)
                    wmma::mma_sync(c[i][j], a[i], b[j], c[i][j]);
        }
        __syncthreads();
    }

#pragma unroll
    for (int i = 0; i < 2; i++)
#pragma unroll
        for (int j = 0; j < 2; j++)
            wmma::store_matrix_sync(Cs + (wrow * 32 + i * 16) * C_LD + wcol * 32 + j * 16,
                                    c[i][j], C_LD, wmma::mem_row_major);
    __syncthreads();

    if (tid < BM) {
        int grow = row0 + tid;
        if (grow < M) {
            const float* src = Cs + tid * C_LD;
            __half* dst = C + (size_t)grow * Ncols + col0;
#pragma unroll
            for (int cB = 0; cB < BN; cB += 8) {
                __half2 p0 = __floats2half2_rn(src[cB + 0], src[cB + 1]);
                __half2 p1 = __floats2half2_rn(src[cB + 2], src[cB + 3]);
                __half2 p2 = __floats2half2_rn(src[cB + 4], src[cB + 5]);
                __half2 p3 = __floats2half2_rn(src[cB + 6], src[cB + 7]);
                uint4 o;
                o.x = *(unsigned*)&p0; o.y = *(unsigned*)&p1;
                o.z = *(unsigned*)&p2; o.w = *(unsigned*)&p3;
                *(uint4*)(dst + cB) = o;
            }
        }
    }
}

__global__ __launch_bounds__(256) void k_gemm1(int M) {
    gemm_wmma_body(g_xh, g_w1h, g_h1h, 0, M, HID);
}

__global__ __launch_bounds__(256) void k_gemm2(int rowBase, int M) {
    gemm_wmma_body(g_z1h, g_w2h, g_h2h, rowBase, M, OUT_CH);
}

// ---------------- CSR aggregation (pure row-sum; rows pre-scaled) ----------
__device__ __forceinline__ void acc8_add(float* acc, uint4 v) {
    const __half2* p = (const __half2*)&v;
#pragma unroll
    for (int j = 0; j < 4; j++) {
        float2 f = __half22float2(p[j]);
        acc[2 * j]     += f.x;
        acc[2 * j + 1] += f.y;
    }
}

// agg1 over node range [base, limit): one warp/node.
__global__ __launch_bounds__(256) void k_agg1(const float* __restrict__ bias,
                                              int base, int limit)
{
    int node = base + ((blockIdx.x * blockDim.x + threadIdx.x) >> 5);
    if (node >= limit) return;
    int lane = threadIdx.x & 31;
    const unsigned FULL = 0xffffffffu;

    float acc[8] = {0.f, 0.f, 0.f, 0.f, 0.f, 0.f, 0.f, 0.f};
    acc8_add(acc, __ldg((const uint4*)(g_h1h + (size_t)node * HID) + lane));

    int beg = g_rowstart[node];
    int end = g_rowstart[node + 1];
    for (int i0 = beg; i0 < end; i0 += 32) {
        int cnt = end - i0; if (cnt > 32) cnt = 32;
        int myidx = (i0 + lane < end) ? g_csr[i0 + lane] : 0;
        int j = 0;
        for (; j + 8 <= cnt; j += 8) {
            int nb[8];
#pragma unroll
            for (int u = 0; u < 8; u++) nb[u] = __shfl_sync(FULL, myidx, j + u);
            uint4 v[8];
#pragma unroll
            for (int u = 0; u < 8; u++)
                v[u] = __ldg((const uint4*)(g_h1h + (size_t)nb[u] * HID) + lane);
#pragma unroll
            for (int u = 0; u < 8; u++) acc8_add(acc, v[u]);
        }
        for (; j < cnt; j++) {
            int nb = __shfl_sync(FULL, myidx, j);
            acc8_add(acc, __ldg((const uint4*)(g_h1h + (size_t)nb * HID) + lane));
        }
    }

    float di = g_dinv[node];
    float4 b0 = __ldg((const float4*)bias + lane * 2);
    float4 b1v = __ldg((const float4*)bias + lane * 2 + 1);
    float o[8];
    o[0] = fmaxf(acc[0] * di + b0.x, 0.f) * di;
    o[1] = fmaxf(acc[1] * di + b0.y, 0.f) * di;
    o[2] = fmaxf(acc[2] * di + b0.z, 0.f) * di;
    o[3] = fmaxf(acc[3] * di + b0.w, 0.f) * di;
    o[4] = fmaxf(acc[4] * di + b1v.x, 0.f) * di;
    o[5] = fmaxf(acc[5] * di + b1v.y, 0.f) * di;
    o[6] = fmaxf(acc[6] * di + b1v.z, 0.f) * di;
    o[7] = fmaxf(acc[7] * di + b1v.w, 0.f) * di;
    __half2 h0 = __floats2half2_rn(o[0], o[1]);
    __half2 h1 = __floats2half2_rn(o[2], o[3]);
    __half2 h2 = __floats2half2_rn(o[4], o[5]);
    __half2 h3 = __floats2half2_rn(o[6], o[7]);
    uint4 ov;
    ov.x = *(unsigned*)&h0; ov.y = *(unsigned*)&h1;
    ov.z = *(unsigned*)&h2; ov.w = *(unsigned*)&h3;
    *((uint4*)(g_z1h + (size_t)node * HID) + lane) = ov;
}

// agg2: one node per 16-lane group; group-local shfl.
__global__ __launch_bounds__(256) void k_agg2(const float* __restrict__ bias, int n)
{
    int node = (blockIdx.x * blockDim.x + threadIdx.x) >> 4;
    if (node >= n) return;
    int lane = threadIdx.x & 31;
    int grp  = lane >> 4;
    int l16  = lane & 15;
    unsigned GM = 0xFFFFu << (grp * 16);

    float acc[8] = {0.f, 0.f, 0.f, 0.f, 0.f, 0.f, 0.f, 0.f};
    acc8_add(acc, __ldg((const uint4*)(g_h2h + (size_t)node * OUT_CH) + l16));

    int beg = g_rowstart[node];
    int end = g_rowstart[node + 1];
    for (int i0 = beg; i0 < end; i0 += 16) {
        int cnt = end - i0; if (cnt > 16) cnt = 16;
        int myidx = (i0 + l16 < end) ? g_csr[i0 + l16] : 0;
        int j = 0;
        for (; j + 8 <= cnt; j += 8) {
            int nb[8];
#pragma unroll
            for (int u = 0; u < 8; u++) nb[u] = __shfl_sync(GM, myidx, j + u, 16);
            uint4 v[8];
#pragma unroll
            for (int u = 0; u < 8; u++)
                v[u] = __ldg((const uint4*)(g_h2h + (size_t)nb[u] * OUT_CH) + l16);
#pragma unroll
            for (int u = 0; u < 8; u++) acc8_add(acc, v[u]);
        }
        for (; j < cnt; j++) {
            int nb = __shfl_sync(GM, myidx, j, 16);
            acc8_add(acc, __ldg((const uint4*)(g_h2h + (size_t)nb * OUT_CH) + l16));
        }
    }

    float di = g_dinv[node];
    float4 b0 = __ldg((const float4*)bias + l16 * 2);
    float4 b1v = __ldg((const float4*)bias + l16 * 2 + 1);
    __half2 h0 = __floats2half2_rn(acc[0] * di + b0.x,  acc[1] * di + b0.y);
    __half2 h1 = __floats2half2_rn(acc[2] * di + b0.z,  acc[3] * di + b0.w);
    __half2 h2 = __floats2half2_rn(acc[4] * di + b1v.x, acc[5] * di + b1v.y);
    __half2 h3 = __floats2half2_rn(acc[6] * di + b1v.z, acc[7] * di + b1v.w);
    uint4 ov;
    ov.x = *(unsigned*)&h0; ov.y = *(unsigned*)&h1;
    ov.z = *(unsigned*)&h2; ov.w = *(unsigned*)&h3;
    *((uint4*)(g_z2h + (size_t)node * OUT_CH) + l16) = ov;
}

// ---------------- decoder: 4 edges per 16-lane group (8 per warp) ----------
__global__ __launch_bounds__(256) void k_decode(
    const int* __restrict__ ei, float* __restrict__ out, int E, int n)
{
    int warp = (blockIdx.x * blockDim.x + threadIdx.x) >> 5;
    int lane = threadIdx.x & 31;
    int grp  = lane >> 4;
    int l16  = lane & 15;
    int e0 = warp * 8 + grp * 4;   // this group's four edges
    if (e0 >= E) return;

    uint4 va[4], vb[4];
    bool ok[4];
#pragma unroll
    for (int u = 0; u < 4; u++) {
        int e = e0 + u;
        bool has = (e < E);
        int s = has ? __ldg(&ei[e]) : 0;
        int d = has ? __ldg(&ei[(size_t)E + e]) : 0;
        ok[u] = has && (unsigned)s < (unsigned)n && (unsigned)d < (unsigned)n;
        va[u] = make_uint4(0, 0, 0, 0);
        vb[u] = make_uint4(0, 0, 0, 0);
        if (ok[u]) {
            va[u] = __ldg((const uint4*)(g_z2h + (size_t)s * OUT_CH) + l16);
            vb[u] = __ldg((const uint4*)(g_z2h + (size_t)d * OUT_CH) + l16);
        }
    }

    float p[4];
#pragma unroll
    for (int u = 0; u < 4; u++) {
        const __half2* pa = (const __half2*)&va[u];
        const __half2* pb = (const __half2*)&vb[u];
        float acc = 0.f;
#pragma unroll
        for (int j = 0; j < 4; j++) {
            float2 a = __half22float2(pa[j]);
            float2 b = __half22float2(pb[j]);
            acc += a.x * b.x + a.y * b.y;
        }
        p[u] = acc;
    }
#pragma unroll
    for (int off = 8; off > 0; off >>= 1) {
#pragma unroll
        for (int u = 0; u < 4; u++)
            p[u] += __shfl_down_sync(0xffffffffu, p[u], off, 16);
    }
    if (l16 == 0) {
#pragma unroll
        for (int u = 0; u < 4; u++)
            if (e0 + u < E) out[e0 + u] = p[u];
    }
}

// ---------------- launch ---------------------------------------------------
extern "C" void kernel_launch(void* const* d_in, const int* in_sizes, int n_in,
                              void* d_out, int out_size)
{
    const float* x  = (const float*)d_in[0];
    const int*   ei = (const int*)d_in[1];   // [2, E] indices, staged as int32
    const float* W1 = (const float*)d_in[2];
    const float* b1 = (const float*)d_in[3];
    const float* W2 = (const float*)d_in[4];
    const float* b2 = (const float*)d_in[5];
    float* out = (float*)d_out;

    int n = in_sizes[0] / IN_CH;    // 50000
    int E = in_sizes[1] / 2;        // 1600000
    int nh = ((n / 2 + BM - 1) / BM) * BM;   // chunk split, BM-aligned
    if (nh > n) nh = n;
    int nb = (n + 255) / 256;       // scan blocks (<=256)
    int total4 = n * (IN_CH / 4);   // float4 chunks of x
    int half4 = total4 / 2;

    // Streams/events: capture-legal fork/join; runs only at capture time.
    cudaStream_t s2;
    cudaStreamCreate(&s2);
    cudaEvent_t evFork, evXa, evG1, evA, evG2a;
    cudaEventCreateWithFlags(&evFork, cudaEventDisableTiming);
    cudaEventCreateWithFlags(&evXa, cudaEventDisableTiming);
    cudaEventCreateWithFlags(&evG1, cudaEventDisableTiming);
    cudaEventCreateWithFlags(&evA, cudaEventDisableTiming);
    cudaEventCreateWithFlags(&evG2a, cudaEventDisableTiming);

    cudaEventRecord(evFork, 0);
    cudaStreamWaitEvent(s2, evFork, 0);

    // Branch A (default stream): first half of cvt_x, then CSR build
    k_cvt_x<<<(half4 + 255) / 256, 256>>>(x, 0, half4);
    cudaEventRecord(evXa, 0);
    k_zero_cnt<<<(n + 255) / 256, 256>>>(n);
    k_count4<<<(E / 4 + 255) / 256, 256>>>(ei, E, n);
    k_scan1<<<nb, 256>>>(n);
    k_scan2<<<1, 256>>>(nb, n);
    k_scan3<<<nb, 256>>>(n);
    k_fill4<<<(E / 4 + 255) / 256, 256>>>(ei, E, n);

    // Branch B (s2): second half cvt_x, weights, gemm1 (waits for A's half)
    k_cvt_x<<<((total4 - half4) + 255) / 256, 256, 0, s2>>>(x, half4, total4);
    k_cvt_w<<<((GK * HID + GK * OUT_CH) / 4 + 255) / 256, 256, 0, s2>>>(W1, W2);
    cudaStreamWaitEvent(s2, evXa, 0);
    {
        dim3 grid(HID / BN, (n + BM - 1) / BM);
        k_gemm1<<<grid, 256, 0, s2>>>(n);
    }
    cudaEventRecord(evG1, s2);
    cudaStreamWaitEvent(0, evG1, 0);

    // Joined: scale h1 rows, then pipelined agg1 / gemm2 over two node chunks
    k_scale_h1<<<(n * (HID / 8) + 255) / 256, 256>>>(n);

    k_agg1<<<(nh * 32 + 255) / 256, 256>>>(b1, 0, nh);           // chunk 0
    cudaEventRecord(evA, 0);

    cudaStreamWaitEvent(s2, evA, 0);                             // gemm2 chunk 0 || agg1 chunk 1
    {
        dim3 grid(OUT_CH / BN, nh / BM);
        k_gemm2<<<grid, 256, 0, s2>>>(0, n);
    }
    cudaEventRecord(evG2a, s2);

    k_agg1<<<((n - nh) * 32 + 255) / 256, 256>>>(b1, nh, n);     // chunk 1
    {
        dim3 grid(OUT_CH / BN, (n - nh + BM - 1) / BM);
        k_gemm2<<<grid, 256>>>(nh, n);
    }
    cudaStreamWaitEvent(0, evG2a, 0);

    // agg2 (node per 16-lane group) and decode (8 edges/warp)
    k_agg2<<<(n * 16 + 255) / 256, 256>>>(b2, n);
    k_decode<<<(((E + 7) / 8) * 32 + 255) / 256, 256>>>(ei, out, E, n);

    cudaEventDestroy(evFork);
    cudaEventDestroy(evXa);
    cudaEventDestroy(evG1);
    cudaEventDestroy(evA);
    cudaEventDestroy(evG2a);
    cudaStreamDestroy(s2);
}

// round 14
// speedup vs baseline: 1.2618x; 1.0001x over previous
#include <cuda_runtime.h>
#include <cuda_fp16.h>
#include <mma.h>
#include <cstdint>

using namespace nvcuda;

// Problem constants (GAE: GCN encoder x2 + inner-product decoder)
#define NN 50000
#define NE 1600000
#define IN_CH 256
#define HID 256
#define OUT_CH 128
#define GK 256   // K dim of both GEMMs

// ---------------- scratch (static device globals; no allocation) ----------
__device__ __align__(256) int    g_cnt[NN];
__device__ __align__(256) int    g_rowstart[NN + 1];
__device__ __align__(256) int    g_pos[NN];
__device__ __align__(256) float  g_dinv[NN];
__device__ __align__(256) int    g_csr[NE];
__device__ __align__(256) int    g_blksum[256];
__device__ __align__(256) int    g_blkoff[256];
__device__ __align__(256) __half g_xh[(size_t)NN * IN_CH];    // fp16 x (unscaled)
__device__ __align__(256) __half g_w1h[GK * HID];             // fp16 W1
__device__ __align__(256) __half g_w2h[GK * OUT_CH];          // fp16 W2
__device__ __align__(256) __half g_h1h[(size_t)NN * HID];     // fp16: x@W1, then *= dinv[row]
__device__ __align__(256) __half g_z1h[(size_t)NN * HID];     // fp16: relu(agg*di+b1)*di
__device__ __align__(256) __half g_h2h[(size_t)NN * OUT_CH];  // fp16: z1h@W2 (rows pre-scaled)
__device__ __align__(256) __half g_z2h[(size_t)NN * OUT_CH];  // fp16: agg*di+b2

// ---------------- degree / CSR build --------------------------------------
__global__ void k_zero_cnt(int n) {
    int i = blockIdx.x * blockDim.x + threadIdx.x;
    if (i < n) g_cnt[i] = 0;
}

// 4 edges per thread via int4 (E is a multiple of 4)
__global__ void k_count4(const int* __restrict__ ei, int E, int n) {
    int i = blockIdx.x * blockDim.x + threadIdx.x;
    if (i < E / 4) {
        int4 d = __ldg((const int4*)(ei + E) + i);
        if ((unsigned)d.x < (unsigned)n) atomicAdd(&g_cnt[d.x], 1);
        if ((unsigned)d.y < (unsigned)n) atomicAdd(&g_cnt[d.y], 1);
        if ((unsigned)d.z < (unsigned)n) atomicAdd(&g_cnt[d.z], 1);
        if ((unsigned)d.w < (unsigned)n) atomicAdd(&g_cnt[d.w], 1);
    }
}

// multi-block exclusive scan: scan1 (block sums) -> scan2 (scan sums) -> scan3
__global__ void k_scan1(int n) {
    int t = threadIdx.x;
    int i = blockIdx.x * 256 + t;
    int v = (i < n) ? g_cnt[i] : 0;
    __shared__ int sm[256];
    sm[t] = v;
    __syncthreads();
    for (int off = 1; off < 256; off <<= 1) {
        int u = (t >= off) ? sm[t - off] : 0;
        __syncthreads();
        sm[t] += u;
        __syncthreads();
    }
    if (t == 255) g_blksum[blockIdx.x] = sm[255];
}

__global__ void k_scan2(int nb, int n) {
    int t = threadIdx.x;
    int v = (t < nb) ? g_blksum[t] : 0;
    __shared__ int sm[256];
    sm[t] = v;
    __syncthreads();
    for (int off = 1; off < 256; off <<= 1) {
        int u = (t >= off) ? sm[t - off] : 0;
        __syncthreads();
        sm[t] += u;
        __syncthreads();
    }
    if (t < nb) g_blkoff[t] = sm[t] - v;   // exclusive
    if (t == 255) g_rowstart[n] = sm[255]; // total
}

__global__ void k_scan3(int n) {
    int t = threadIdx.x;
    int i = blockIdx.x * 256 + t;
    int v = (i < n) ? g_cnt[i] : 0;
    __shared__ int sm[256];
    sm[t] = v;
    __syncthreads();
    for (int off = 1; off < 256; off <<= 1) {
        int u = (t >= off) ? sm[t - off] : 0;
        __syncthreads();
        sm[t] += u;
        __syncthreads();
    }
    if (i < n) {
        int excl = sm[t] - v + g_blkoff[blockIdx.x];
        g_rowstart[i] = excl;
        g_pos[i] = excl;
        g_dinv[i] = rsqrtf((float)(v + 1));
    }
}

// 4 edges per thread
__global__ void k_fill4(const int* __restrict__ ei, int E, int n) {
    int i = blockIdx.x * blockDim.x + threadIdx.x;
    if (i < E / 4) {
        int4 s4 = __ldg((const int4*)ei + i);
        int4 d4 = __ldg((const int4*)(ei + E) + i);
        int ss[4] = {s4.x, s4.y, s4.z, s4.w};
        int dd[4] = {d4.x, d4.y, d4.z, d4.w};
#pragma unroll
        for (int u = 0; u < 4; u++) {
            if ((unsigned)ss[u] < (unsigned)n && (unsigned)dd[u] < (unsigned)n) {
                int p = atomicAdd(&g_pos[dd[u]], 1);
                if ((unsigned)p < (unsigned)NE) g_csr[p] = ss[u];
            }
        }
    }
}

// ---------------- conversions ----------------------------------------------
__device__ __forceinline__ void cvt_chunk(const float* __restrict__ S,
                                          __half* __restrict__ D, int i) {
    float4 v = __ldg((const float4*)S + i);
    __half2 lo = __floats2half2_rn(v.x, v.y);
    __half2 hi = __floats2half2_rn(v.z, v.w);
    uint2 o; o.x = *(unsigned*)&lo; o.y = *(unsigned*)&hi;
    *((uint2*)D + i) = o;
}

__global__ void k_cvt_x(const float* __restrict__ x, int lo4, int hi4) {
    int i = lo4 + blockIdx.x * blockDim.x + threadIdx.x;
    if (i < hi4) cvt_chunk(x, g_xh, i);
}

__global__ void k_cvt_w(const float* __restrict__ W1, const float* __restrict__ W2) {
    int i = blockIdx.x * blockDim.x + threadIdx.x;
    const int C1 = GK * HID / 4;
    const int C2 = GK * OUT_CH / 4;
    if (i < C1) cvt_chunk(W1, g_w1h, i);
    else if (i < C1 + C2) cvt_chunk(W2, g_w2h, i - C1);
}

// post-join: h1h[row,:] *= dinv[row]
__global__ void k_scale_h1(int n) {
    int i = blockIdx.x * blockDim.x + threadIdx.x;   // one uint4 (8 halves)
    int total = n * (HID / 8);
    if (i >= total) return;
    float di = g_dinv[i / (HID / 8)];
    uint4 v = *((const uint4*)g_h1h + i);
    __half2* p = (__half2*)&v;
#pragma unroll
    for (int j = 0; j < 4; j++) {
        float2 f = __half22float2(p[j]);
        p[j] = __floats2half2_rn(f.x * di, f.y * di);
    }
    *((uint4*)g_h1h + i) = v;
}

// ---------------- wmma fp16 GEMM (double-buffered): C = A[M,256]@B[256,N] --
#define BM 128
#define BN 64
#define BK 32
#define A_LD 40   // BK + 8 pad (halves)
#define B_LD 72   // BN + 8 pad (halves)
#define C_LD 68   // BN + 4 pad (floats)
#define A_BUF (BM * A_LD)   // 5120 halves
#define B_BUF (BK * B_LD)   // 2304 halves

__device__ __forceinline__ void gemm_wmma_body(
    const __half* __restrict__ A, const __half* __restrict__ B,
    __half* __restrict__ C, int rowBase, int M, int Ncols)
{
    // tiles double-buffered (2*(10240+4608)=29696 B) unioned with C staging (34816 B)
    __shared__ __align__(16) char sm[BM * C_LD * 4];
    __half* As = (__half*)sm;                      // [2][A_BUF]
    __half* Bs = As + 2 * A_BUF;                   // [2][B_BUF]
    float*  Cs = (float*)sm;                       // [BM][C_LD]

    int tid = threadIdx.x;
    int warp = tid >> 5;
    int wrow = warp >> 1;
    int wcol = warp & 1;
    int row0 = rowBase + blockIdx.y * BM;
    int col0 = blockIdx.x * BN;

    // per-thread load slots
    int ar0 = tid >> 1;                 // A rows handled: ar0 (t=0), ar0+... two uint4 per thread
    // A: 512 uint4 per tile; thread t covers v = t and t+256
    // B: 256 uint4 per tile; thread t covers one

    wmma::fragment<wmma::accumulator, 16, 16, 16, float> c[2][2];
#pragma unroll
    for (int i = 0; i < 2; i++)
#pragma unroll
        for (int j = 0; j < 2; j++) wmma::fill_fragment(c[i][j], 0.f);

    // prologue: load tile 0 into buffer 0
    {
#pragma unroll
        for (int t = 0; t < 2; t++) {
            int v = tid + t * 256;
            int r = v >> 2;
            int kc = (v & 3) * 8;
            int grow = row0 + r;
            uint4 val = make_uint4(0u, 0u, 0u, 0u);
            if (grow < M) val = *(const uint4*)(A + (size_t)grow * GK + kc);
            *(uint4*)(As + r * A_LD + kc) = val;
        }
        int r = tid >> 3;
        int c8 = (tid & 7) * 8;
        uint4 val = *(const uint4*)(B + (size_t)r * Ncols + col0 + c8);
        *(uint4*)(Bs + r * B_LD + c8) = val;
    }
    __syncthreads();

    for (int k0 = 0; k0 < GK; k0 += BK) {
        int cur = (k0 / BK) & 1;
        int nxt = cur ^ 1;
        bool more = (k0 + BK) < GK;

        // prefetch next tile into registers (independent of smem)
        uint4 pa[2], pb;
        if (more) {
#pragma unroll
            for (int t = 0; t < 2; t++) {
                int v = tid + t * 256;
                int r = v >> 2;
                int kc = (v & 3) * 8;
                int grow = row0 + r;
                pa[t] = make_uint4(0u, 0u, 0u, 0u);
                if (grow < M) pa[t] = *(const uint4*)(A + (size_t)grow * GK + k0 + BK + kc);
            }
            int r = tid >> 3;
            int c8 = (tid & 7) * 8;
            pb = *(const uint4*)(B + (size_t)(k0 + BK + r) * Ncols + col0 + c8);
        }

        // compute on current buffer
        const __half* Ac = As + cur * A_BUF;
        const __half* Bc = Bs + cur * B_BUF;
#pragma unroll
        for (int kk = 0; kk < BK; kk += 16) {
            wmma::fragment<wmma::matrix_a, 16, 16, 16, __half, wmma::row_major> a[2];
            wmma::fragment<wmma::matrix_b, 16, 16, 16, __half, wmma::row_major> b[2];
#pragma unroll
            for (int i = 0; i < 2; i++)
                wmma::load_matrix_sync(a[i], Ac + (wrow * 32 + i * 16) * A_LD + kk, A_LD);
#pragma unroll
            for (int j = 0; j < 2; j++)
                wmma::load_matrix_sync(b[j], Bc + kk * B_LD + wcol * 32 + j * 16, B_LD);
#pragma unroll
            for (int i = 0; i < 2; i++)
#pragma unroll
                for (int j = 0; j < 2; j++)
                    wmma::mma_sync(c[i][j], a[i], b[j], c[i][j]);
        }

        // store prefetched tile into the other buffer
        if (more) {
            __half* An = As + nxt * A_BUF;
            __half* Bn = Bs + nxt * B_BUF;
#pragma unroll
            for (int t = 0; t < 2; t++) {
                int v = tid + t * 256;
                int r = v >> 2;
                int kc = (v & 3) * 8;
                *(uint4*)(An + r * A_LD + kc) = pa[t];
            }
            int r = tid >> 3;
            int c8 = (tid & 7) * 8;
            *(uint4*)(Bn + r * B_LD + c8) = pb;
        }
        __syncthreads();
    }

    // stage fp32 result in smem, convert to fp16, write out
#pragma unroll
    for (int i = 0; i < 2; i++)
#pragma unroll
        for (int j = 0; j < 2; j++)
            wmma::store_matrix_sync(Cs + (wrow * 32 + i * 16) * C_LD + wcol * 32 + j * 16,
                                    c[i][j], C_LD, wmma::mem_row_major);
    __syncthreads();

    if (tid < BM) {
        int grow = row0 + tid;
        if (grow < M) {
            const float* src = Cs + tid * C_LD;
            __half* dst = C + (size_t)grow * Ncols + col0;
#pragma unroll
            for (int cB = 0; cB < BN; cB += 8) {
                __half2 p0 = __floats2half2_rn(src[cB + 0], src[cB + 1]);
                __half2 p1 = __floats2half2_rn(src[cB + 2], src[cB + 3]);
                __half2 p2 = __floats2half2_rn(src[cB + 4], src[cB + 5]);
                __half2 p3 = __floats2half2_rn(src[cB + 6], src[cB + 7]);
                uint4 o;
                o.x = *(unsigned*)&p0; o.y = *(unsigned*)&p1;
                o.z = *(unsigned*)&p2; o.w = *(unsigned*)&p3;
                *(uint4*)(dst + cB) = o;
            }
        }
    }
}

__global__ __launch_bounds__(256) void k_gemm1(int M) {
    gemm_wmma_body(g_xh, g_w1h, g_h1h, 0, M, HID);
}

__global__ __launch_bounds__(256) void k_gemm2(int rowBase, int M) {
    gemm_wmma_body(g_z1h, g_w2h, g_h2h, rowBase, M, OUT_CH);
}

// ---------------- CSR aggregation (pure row-sum; rows pre-scaled) ----------
__device__ __forceinline__ void acc8_add(float* acc, uint4 v) {
    const __half2* p = (const __half2*)&v;
#pragma unroll
    for (int j = 0; j < 4; j++) {
        float2 f = __half22float2(p[j]);
        acc[2 * j]     += f.x;
        acc[2 * j + 1] += f.y;
    }
}

// agg1 over node range [base, limit): one warp/node.
__global__ __launch_bounds__(256) void k_agg1(const float* __restrict__ bias,
                                              int base, int limit)
{
    int node = base + ((blockIdx.x * blockDim.x + threadIdx.x) >> 5);
    if (node >= limit) return;
    int lane = threadIdx.x & 31;
    const unsigned FULL = 0xffffffffu;

    float acc[8] = {0.f, 0.f, 0.f, 0.f, 0.f, 0.f, 0.f, 0.f};
    acc8_add(acc, __ldg((const uint4*)(g_h1h + (size_t)node * HID) + lane));

    int beg = g_rowstart[node];
    int end = g_rowstart[node + 1];
    for (int i0 = beg; i0 < end; i0 += 32) {
        int cnt = end - i0; if (cnt > 32) cnt = 32;
        int myidx = (i0 + lane < end) ? g_csr[i0 + lane] : 0;
        int j = 0;
        for (; j + 8 <= cnt; j += 8) {
            int nb[8];
#pragma unroll
            for (int u = 0; u < 8; u++) nb[u] = __shfl_sync(FULL, myidx, j + u);
            uint4 v[8];
#pragma unroll
            for (int u = 0; u < 8; u++)
                v[u] = __ldg((const uint4*)(g_h1h + (size_t)nb[u] * HID) + lane);
#pragma unroll
            for (int u = 0; u < 8; u++) acc8_add(acc, v[u]);
        }
        for (; j < cnt; j++) {
            int nb = __shfl_sync(FULL, myidx, j);
            acc8_add(acc, __ldg((const uint4*)(g_h1h + (size_t)nb * HID) + lane));
        }
    }

    float di = g_dinv[node];
    float4 b0 = __ldg((const float4*)bias + lane * 2);
    float4 b1v = __ldg((const float4*)bias + lane * 2 + 1);
    float o[8];
    o[0] = fmaxf(acc[0] * di + b0.x, 0.f) * di;
    o[1] = fmaxf(acc[1] * di + b0.y, 0.f) * di;
    o[2] = fmaxf(acc[2] * di + b0.z, 0.f) * di;
    o[3] = fmaxf(acc[3] * di + b0.w, 0.f) * di;
    o[4] = fmaxf(acc[4] * di + b1v.x, 0.f) * di;
    o[5] = fmaxf(acc[5] * di + b1v.y, 0.f) * di;
    o[6] = fmaxf(acc[6] * di + b1v.z, 0.f) * di;
    o[7] = fmaxf(acc[7] * di + b1v.w, 0.f) * di;
    __half2 h0 = __floats2half2_rn(o[0], o[1]);
    __half2 h1 = __floats2half2_rn(o[2], o[3]);
    __half2 h2 = __floats2half2_rn(o[4], o[5]);
    __half2 h3 = __floats2half2_rn(o[6], o[7]);
    uint4 ov;
    ov.x = *(unsigned*)&h0; ov.y = *(unsigned*)&h1;
    ov.z = *(unsigned*)&h2; ov.w = *(unsigned*)&h3;
    *((uint4*)(g_z1h + (size_t)node * HID) + lane) = ov;
}

// agg2: one node per 16-lane group; group-local shfl.
__global__ __launch_bounds__(256) void k_agg2(const float* __restrict__ bias, int n)
{
    int node = (blockIdx.x * blockDim.x + threadIdx.x) >> 4;
    if (node >= n) return;
    int lane = threadIdx.x & 31;
    int grp  = lane >> 4;
    int l16  = lane & 15;
    unsigned GM = 0xFFFFu << (grp * 16);

    float acc[8] = {0.f, 0.f, 0.f, 0.f, 0.f, 0.f, 0.f, 0.f};
    acc8_add(acc, __ldg((const uint4*)(g_h2h + (size_t)node * OUT_CH) + l16));

    int beg = g_rowstart[node];
    int end = g_rowstart[node + 1];
    for (int i0 = beg; i0 < end; i0 += 16) {
        int cnt = end - i0; if (cnt > 16) cnt = 16;
        int myidx = (i0 + l16 < end) ? g_csr[i0 + l16] : 0;
        int j = 0;
        for (; j + 8 <= cnt; j += 8) {
            int nb[8];
#pragma unroll
            for (int u = 0; u < 8; u++) nb[u] = __shfl_sync(GM, myidx, j + u, 16);
            uint4 v[8];
#pragma unroll
            for (int u = 0; u < 8; u++)
                v[u] = __ldg((const uint4*)(g_h2h + (size_t)nb[u] * OUT_CH) + l16);
#pragma unroll
            for (int u = 0; u < 8; u++) acc8_add(acc, v[u]);
        }
        for (; j < cnt; j++) {
            int nb = __shfl_sync(GM, myidx, j, 16);
            acc8_add(acc, __ldg((const uint4*)(g_h2h + (size_t)nb * OUT_CH) + l16));
        }
    }

    float di = g_dinv[node];
    float4 b0 = __ldg((const float4*)bias + l16 * 2);
    float4 b1v = __ldg((const float4*)bias + l16 * 2 + 1);
    __half2 h0 = __floats2half2_rn(acc[0] * di + b0.x,  acc[1] * di + b0.y);
    __half2 h1 = __floats2half2_rn(acc[2] * di + b0.z,  acc[3] * di + b0.w);
    __half2 h2 = __floats2half2_rn(acc[4] * di + b1v.x, acc[5] * di + b1v.y);
    __half2 h3 = __floats2half2_rn(acc[6] * di + b1v.z, acc[7] * di + b1v.w);
    uint4 ov;
    ov.x = *(unsigned*)&h0; ov.y = *(unsigned*)&h1;
    ov.z = *(unsigned*)&h2; ov.w = *(unsigned*)&h3;
    *((uint4*)(g_z2h + (size_t)node * OUT_CH) + l16) = ov;
}

// ---------------- decoder: 4 edges per 16-lane group (8 per warp) ----------
__global__ __launch_bounds__(256) void k_decode(
    const int* __restrict__ ei, float* __restrict__ out, int E, int n)
{
    int warp = (blockIdx.x * blockDim.x + threadIdx.x) >> 5;
    int lane = threadIdx.x & 31;
    int grp  = lane >> 4;
    int l16  = lane & 15;
    int e0 = warp * 8 + grp * 4;   // this group's four edges
    if (e0 >= E) return;

    uint4 va[4], vb[4];
    bool ok[4];
#pragma unroll
    for (int u = 0; u < 4; u++) {
        int e = e0 + u;
        bool has = (e < E);
        int s = has ? __ldg(&ei[e]) : 0;
        int d = has ? __ldg(&ei[(size_t)E + e]) : 0;
        ok[u] = has && (unsigned)s < (unsigned)n && (unsigned)d < (unsigned)n;
        va[u] = make_uint4(0, 0, 0, 0);
        vb[u] = make_uint4(0, 0, 0, 0);
        if (ok[u]) {
            va[u] = __ldg((const uint4*)(g_z2h + (size_t)s * OUT_CH) + l16);
            vb[u] = __ldg((const uint4*)(g_z2h + (size_t)d * OUT_CH) + l16);
        }
    }

    float p[4];
#pragma unroll
    for (int u = 0; u < 4; u++) {
        const __half2* pa = (const __half2*)&va[u];
        const __half2* pb = (const __half2*)&vb[u];
        float acc = 0.f;
#pragma unroll
        for (int j = 0; j < 4; j++) {
            float2 a = __half22float2(pa[j]);
            float2 b = __half22float2(pb[j]);
            acc += a.x * b.x + a.y * b.y;
        }
        p[u] = acc;
    }
#pragma unroll
    for (int off = 8; off > 0; off >>= 1) {
#pragma unroll
        for (int u = 0; u < 4; u++)
            p[u] += __shfl_down_sync(0xffffffffu, p[u], off, 16);
    }
    if (l16 == 0) {
#pragma unroll
        for (int u = 0; u < 4; u++)
            if (e0 + u < E) out[e0 + u] = p[u];
    }
}

// ---------------- launch ---------------------------------------------------
extern "C" void kernel_launch(void* const* d_in, const int* in_sizes, int n_in,
                              void* d_out, int out_size)
{
    const float* x  = (const float*)d_in[0];
    const int*   ei = (const int*)d_in[1];   // [2, E] indices, staged as int32
    const float* W1 = (const float*)d_in[2];
    const float* b1 = (const float*)d_in[3];
    const float* W2 = (const float*)d_in[4];
    const float* b2 = (const float*)d_in[5];
    float* out = (float*)d_out;

    int n = in_sizes[0] / IN_CH;    // 50000
    int E = in_sizes[1] / 2;        // 1600000
    int nh = ((n / 2 + BM - 1) / BM) * BM;   // chunk split, BM-aligned
    if (nh > n) nh = n;
    int nb = (n + 255) / 256;       // scan blocks (<=256)
    int total4 = n * (IN_CH / 4);   // float4 chunks of x
    int half4 = total4 / 2;

    // Streams/events: capture-legal fork/join; runs only at capture time.
    cudaStream_t s2;
    cudaStreamCreate(&s2);
    cudaEvent_t evFork, evXa, evG1, evA, evG2a;
    cudaEventCreateWithFlags(&evFork, cudaEventDisableTiming);
    cudaEventCreateWithFlags(&evXa, cudaEventDisableTiming);
    cudaEventCreateWithFlags(&evG1, cudaEventDisableTiming);
    cudaEventCreateWithFlags(&evA, cudaEventDisableTiming);
    cudaEventCreateWithFlags(&evG2a, cudaEventDisableTiming);

    cudaEventRecord(evFork, 0);
    cudaStreamWaitEvent(s2, evFork, 0);

    // Branch A (default stream): first half of cvt_x, then CSR build
    k_cvt_x<<<(half4 + 255) / 256, 256>>>(x, 0, half4);
    cudaEventRecord(evXa, 0);
    k_zero_cnt<<<(n + 255) / 256, 256>>>(n);
    k_count4<<<(E / 4 + 255) / 256, 256>>>(ei, E, n);
    k_scan1<<<nb, 256>>>(n);
    k_scan2<<<1, 256>>>(nb, n);
    k_scan3<<<nb, 256>>>(n);
    k_fill4<<<(E / 4 + 255) / 256, 256>>>(ei, E, n);

    // Branch B (s2): second half cvt_x, weights, gemm1 (waits for A's half)
    k_cvt_x<<<((total4 - half4) + 255) / 256, 256, 0, s2>>>(x, half4, total4);
    k_cvt_w<<<((GK * HID + GK * OUT_CH) / 4 + 255) / 256, 256, 0, s2>>>(W1, W2);
    cudaStreamWaitEvent(s2, evXa, 0);
    {
        dim3 grid(HID / BN, (n + BM - 1) / BM);
        k_gemm1<<<grid, 256, 0, s2>>>(n);
    }
    cudaEventRecord(evG1, s2);
    cudaStreamWaitEvent(0, evG1, 0);

    // Joined: scale h1 rows, then pipelined agg1 / gemm2 over two node chunks
    k_scale_h1<<<(n * (HID / 8) + 255) / 256, 256>>>(n);

    k_agg1<<<(nh * 32 + 255) / 256, 256>>>(b1, 0, nh);           // chunk 0
    cudaEventRecord(evA, 0);

    cudaStreamWaitEvent(s2, evA, 0);                             // gemm2 chunk 0 || agg1 chunk 1
    {
        dim3 grid(OUT_CH / BN, nh / BM);
        k_gemm2<<<grid, 256, 0, s2>>>(0, n);
    }
    cudaEventRecord(evG2a, s2);

    k_agg1<<<((n - nh) * 32 + 255) / 256, 256>>>(b1, nh, n);     // chunk 1
    {
        dim3 grid(OUT_CH / BN, (n - nh + BM - 1) / BM);
        k_gemm2<<<grid, 256>>>(nh, n);
    }
    cudaStreamWaitEvent(0, evG2a, 0);

    // agg2 (node per 16-lane group) and decode (8 edges/warp)
    k_agg2<<<(n * 16 + 255) / 256, 256>>>(b2, n);
    k_decode<<<(((E + 7) / 8) * 32 + 255) / 256, 256>>>(ei, out, E, n);

    cudaEventDestroy(evFork);
    cudaEventDestroy(evXa);
    cudaEventDestroy(evG1);
    cudaEventDestroy(evA);
    cudaEventDestroy(evG2a);
    cudaStreamDestroy(s2);
}

// round 15
// speedup vs baseline: 1.2714x; 1.0076x over previous
#include <cuda_runtime.h>
#include <cuda_fp16.h>
#include <mma.h>
#include <cstdint>

using namespace nvcuda;

// Problem constants (GAE: GCN encoder x2 + inner-product decoder)
#define NN 50000
#define NE 1600000
#define IN_CH 256
#define HID 256
#define OUT_CH 128
#define GK 256   // K dim of both GEMMs

// ---------------- scratch (static device globals; no allocation) ----------
__device__ __align__(256) int    g_cnt[NN];
__device__ __align__(256) int    g_rowstart[NN + 1];
__device__ __align__(256) int    g_pos[NN];
__device__ __align__(256) float  g_dinv[NN];
__device__ __align__(256) int    g_csr[NE];
__device__ __align__(256) int    g_blksum[256];
__device__ __align__(256) int    g_blkoff[256];
__device__ __align__(256) __half g_xh[(size_t)NN * IN_CH];    // fp16 x (unscaled)
__device__ __align__(256) __half g_w1h[GK * HID];             // fp16 W1
__device__ __align__(256) __half g_w2h[GK * OUT_CH];          // fp16 W2
__device__ __align__(256) __half g_h1h[(size_t)NN * HID];     // fp16: x@W1, then *= dinv[row]
__device__ __align__(256) __half g_z1h[(size_t)NN * HID];     // fp16: relu(agg*di+b1)*di
__device__ __align__(256) __half g_h2h[(size_t)NN * OUT_CH];  // fp16: z1h@W2 (rows pre-scaled)
__device__ __align__(256) __half g_z2h[(size_t)NN * OUT_CH];  // fp16: agg*di+b2

// ---------------- degree / CSR build --------------------------------------
__global__ void k_zero_cnt(int n) {
    int i = blockIdx.x * blockDim.x + threadIdx.x;
    if (i < n) g_cnt[i] = 0;
}

// 8 edges per thread via 2x int4 (E is a multiple of 8)
__global__ void k_count8(const int* __restrict__ ei, int E, int n) {
    int i = blockIdx.x * blockDim.x + threadIdx.x;
    if (i < E / 8) {
        int4 d0 = __ldg((const int4*)(ei + E) + 2 * i);
        int4 d1 = __ldg((const int4*)(ei + E) + 2 * i + 1);
        int dd[8] = {d0.x, d0.y, d0.z, d0.w, d1.x, d1.y, d1.z, d1.w};
#pragma unroll
        for (int u = 0; u < 8; u++)
            if ((unsigned)dd[u] < (unsigned)n) atomicAdd(&g_cnt[dd[u]], 1);
    }
}

// multi-block exclusive scan: scan1 (block sums) -> scan2 (scan sums) -> scan3
__global__ void k_scan1(int n) {
    int t = threadIdx.x;
    int i = blockIdx.x * 256 + t;
    int v = (i < n) ? g_cnt[i] : 0;
    __shared__ int sm[256];
    sm[t] = v;
    __syncthreads();
    for (int off = 1; off < 256; off <<= 1) {
        int u = (t >= off) ? sm[t - off] : 0;
        __syncthreads();
        sm[t] += u;
        __syncthreads();
    }
    if (t == 255) g_blksum[blockIdx.x] = sm[255];
}

__global__ void k_scan2(int nb, int n) {
    int t = threadIdx.x;
    int v = (t < nb) ? g_blksum[t] : 0;
    __shared__ int sm[256];
    sm[t] = v;
    __syncthreads();
    for (int off = 1; off < 256; off <<= 1) {
        int u = (t >= off) ? sm[t - off] : 0;
        __syncthreads();
        sm[t] += u;
        __syncthreads();
    }
    if (t < nb) g_blkoff[t] = sm[t] - v;   // exclusive
    if (t == 255) g_rowstart[n] = sm[255]; // total
}

__global__ void k_scan3(int n) {
    int t = threadIdx.x;
    int i = blockIdx.x * 256 + t;
    int v = (i < n) ? g_cnt[i] : 0;
    __shared__ int sm[256];
    sm[t] = v;
    __syncthreads();
    for (int off = 1; off < 256; off <<= 1) {
        int u = (t >= off) ? sm[t - off] : 0;
        __syncthreads();
        sm[t] += u;
        __syncthreads();
    }
    if (i < n) {
        int excl = sm[t] - v + g_blkoff[blockIdx.x];
        g_rowstart[i] = excl;
        g_pos[i] = excl;
        g_dinv[i] = rsqrtf((float)(v + 1));
    }
}

// 8 edges per thread
__global__ void k_fill8(const int* __restrict__ ei, int E, int n) {
    int i = blockIdx.x * blockDim.x + threadIdx.x;
    if (i < E / 8) {
        int4 s0 = __ldg((const int4*)ei + 2 * i);
        int4 s1 = __ldg((const int4*)ei + 2 * i + 1);
        int4 d0 = __ldg((const int4*)(ei + E) + 2 * i);
        int4 d1 = __ldg((const int4*)(ei + E) + 2 * i + 1);
        int ss[8] = {s0.x, s0.y, s0.z, s0.w, s1.x, s1.y, s1.z, s1.w};
        int dd[8] = {d0.x, d0.y, d0.z, d0.w, d1.x, d1.y, d1.z, d1.w};
#pragma unroll
        for (int u = 0; u < 8; u++) {
            if ((unsigned)ss[u] < (unsigned)n && (unsigned)dd[u] < (unsigned)n) {
                int p = atomicAdd(&g_pos[dd[u]], 1);
                if ((unsigned)p < (unsigned)NE) g_csr[p] = ss[u];
            }
        }
    }
}

// ---------------- conversions ----------------------------------------------
__device__ __forceinline__ void cvt_chunk(const float* __restrict__ S,
                                          __half* __restrict__ D, int i) {
    float4 v = __ldg((const float4*)S + i);
    __half2 lo = __floats2half2_rn(v.x, v.y);
    __half2 hi = __floats2half2_rn(v.z, v.w);
    uint2 o; o.x = *(unsigned*)&lo; o.y = *(unsigned*)&hi;
    *((uint2*)D + i) = o;
}

__global__ void k_cvt_x(const float* __restrict__ x, int lo4, int hi4) {
    int i = lo4 + blockIdx.x * blockDim.x + threadIdx.x;
    if (i < hi4) cvt_chunk(x, g_xh, i);
}

// second half of x + both weight matrices in one launch
__global__ void k_cvt_xw(const float* __restrict__ x, int lo4, int hi4,
                         const float* __restrict__ W1, const float* __restrict__ W2) {
    int i = blockIdx.x * blockDim.x + threadIdx.x;
    int xs = hi4 - lo4;
    const int C1 = GK * HID / 4;
    const int C2 = GK * OUT_CH / 4;
    if (i < xs) cvt_chunk(x, g_xh, lo4 + i);
    else if (i < xs + C1) cvt_chunk(W1, g_w1h, i - xs);
    else if (i < xs + C1 + C2) cvt_chunk(W2, g_w2h, i - xs - C1);
}

// h1h[row,:] *= dinv[row] over node range [lo, hi)
__global__ void k_scale_h1(int lo, int hi) {
    int i = lo * (HID / 8) + blockIdx.x * blockDim.x + threadIdx.x;
    if (i >= hi * (HID / 8)) return;
    float di = g_dinv[i / (HID / 8)];
    uint4 v = *((const uint4*)g_h1h + i);
    __half2* p = (__half2*)&v;
#pragma unroll
    for (int j = 0; j < 4; j++) {
        float2 f = __half22float2(p[j]);
        p[j] = __floats2half2_rn(f.x * di, f.y * di);
    }
    *((uint4*)g_h1h + i) = v;
}

// ---------------- wmma fp16 GEMM (double-buffered): C = A[M,256]@B[256,N] --
#define BM 128
#define BN 64
#define BK 32
#define A_LD 40   // BK + 8 pad (halves)
#define B_LD 72   // BN + 8 pad (halves)
#define C_LD 68   // BN + 4 pad (floats)
#define A_BUF (BM * A_LD)
#define B_BUF (BK * B_LD)

__device__ __forceinline__ void gemm_wmma_body(
    const __half* __restrict__ A, const __half* __restrict__ B,
    __half* __restrict__ C, int rowBase, int M, int Ncols)
{
    __shared__ __align__(16) char sm[BM * C_LD * 4];
    __half* As = (__half*)sm;                      // [2][A_BUF]
    __half* Bs = As + 2 * A_BUF;                   // [2][B_BUF]
    float*  Cs = (float*)sm;                       // [BM][C_LD]

    int tid = threadIdx.x;
    int warp = tid >> 5;
    int wrow = warp >> 1;
    int wcol = warp & 1;
    int row0 = rowBase + blockIdx.y * BM;
    int col0 = blockIdx.x * BN;

    wmma::fragment<wmma::accumulator, 16, 16, 16, float> c[2][2];
#pragma unroll
    for (int i = 0; i < 2; i++)
#pragma unroll
        for (int j = 0; j < 2; j++) wmma::fill_fragment(c[i][j], 0.f);

    {
#pragma unroll
        for (int t = 0; t < 2; t++) {
            int v = tid + t * 256;
            int r = v >> 2;
            int kc = (v & 3) * 8;
            int grow = row0 + r;
            uint4 val = make_uint4(0u, 0u, 0u, 0u);
            if (grow < M) val = *(const uint4*)(A + (size_t)grow * GK + kc);
            *(uint4*)(As + r * A_LD + kc) = val;
        }
        int r = tid >> 3;
        int c8 = (tid & 7) * 8;
        uint4 val = *(const uint4*)(B + (size_t)r * Ncols + col0 + c8);
        *(uint4*)(Bs + r * B_LD + c8) = val;
    }
    __syncthreads();

    for (int k0 = 0; k0 < GK; k0 += BK) {
        int cur = (k0 / BK) & 1;
        int nxt = cur ^ 1;
        bool more = (k0 + BK) < GK;

        uint4 pa[2], pb;
        if (more) {
#pragma unroll
            for (int t = 0; t < 2; t++) {
                int v = tid + t * 256;
                int r = v >> 2;
                int kc = (v & 3) * 8;
                int grow = row0 + r;
                pa[t] = make_uint4(0u, 0u, 0u, 0u);
                if (grow < M) pa[t] = *(const uint4*)(A + (size_t)grow * GK + k0 + BK + kc);
            }
            int r = tid >> 3;
            int c8 = (tid & 7) * 8;
            pb = *(const uint4*)(B + (size_t)(k0 + BK + r) * Ncols + col0 + c8);
        }

        const __half* Ac = As + cur * A_BUF;
        const __half* Bc = Bs + cur * B_BUF;
#pragma unroll
        for (int kk = 0; kk < BK; kk += 16) {
            wmma::fragment<wmma::matrix_a, 16, 16, 16, __half, wmma::row_major> a[2];
            wmma::fragment<wmma::matrix_b, 16, 16, 16, __half, wmma::row_major> b[2];
#pragma unroll
            for (int i = 0; i < 2; i++)
                wmma::load_matrix_sync(a[i], Ac + (wrow * 32 + i * 16) * A_LD + kk, A_LD);
#pragma unroll
            for (int j = 0; j < 2; j++)
                wmma::load_matrix_sync(b[j], Bc + kk * B_LD + wcol * 32 + j * 16, B_LD);
#pragma unroll
            for (int i = 0; i < 2; i++)
#pragma unroll
                for (int j = 0; j < 2; j++)
                    wmma::mma_sync(c[i][j], a[i], b[j], c[i][j]);
        }

        if (more) {
            __half* An = As + nxt * A_BUF;
            __half* Bn = Bs + nxt * B_BUF;
#pragma unroll
            for (int t = 0; t < 2; t++) {
                int v = tid + t * 256;
                int r = v >> 2;
                int kc = (v & 3) * 8;
                *(uint4*)(An + r * A_LD + kc) = pa[t];
            }
            int r = tid >> 3;
            int c8 = (tid & 7) * 8;
            *(uint4*)(Bn + r * B_LD + c8) = pb;
        }
        __syncthreads();
    }

#pragma unroll
    for (int i = 0; i < 2; i++)
#pragma unroll
        for (int j = 0; j < 2; j++)
            wmma::store_matrix_sync(Cs + (wrow * 32 + i * 16) * C_LD + wcol * 32 + j * 16,
                                    c[i][j], C_LD, wmma::mem_row_major);
    __syncthreads();

    if (tid < BM) {
        int grow = row0 + tid;
        if (grow < M) {
            const float* src = Cs + tid * C_LD;
            __half* dst = C + (size_t)grow * Ncols + col0;
#pragma unroll
            for (int cB = 0; cB < BN; cB += 8) {
                __half2 p0 = __floats2half2_rn(src[cB + 0], src[cB + 1]);
                __half2 p1 = __floats2half2_rn(src[cB + 2], src[cB + 3]);
                __half2 p2 = __floats2half2_rn(src[cB + 4], src[cB + 5]);
                __half2 p3 = __floats2half2_rn(src[cB + 6], src[cB + 7]);
                uint4 o;
                o.x = *(unsigned*)&p0; o.y = *(unsigned*)&p1;
                o.z = *(unsigned*)&p2; o.w = *(unsigned*)&p3;
                *(uint4*)(dst + cB) = o;
            }
        }
    }
}

__global__ __launch_bounds__(256) void k_gemm1(int rowBase, int M) {
    gemm_wmma_body(g_xh, g_w1h, g_h1h, rowBase, M, HID);
}

__global__ __launch_bounds__(256) void k_gemm2(int rowBase, int M) {
    gemm_wmma_body(g_z1h, g_w2h, g_h2h, rowBase, M, OUT_CH);
}

// ---------------- CSR aggregation (pure row-sum; rows pre-scaled) ----------
__device__ __forceinline__ void acc8_add(float* acc, uint4 v) {
    const __half2* p = (const __half2*)&v;
#pragma unroll
    for (int j = 0; j < 4; j++) {
        float2 f = __half22float2(p[j]);
        acc[2 * j]     += f.x;
        acc[2 * j + 1] += f.y;
    }
}

__global__ __launch_bounds__(256) void k_agg1(const float* __restrict__ bias,
                                              int base, int limit)
{
    int node = base + ((blockIdx.x * blockDim.x + threadIdx.x) >> 5);
    if (node >= limit) return;
    int lane = threadIdx.x & 31;
    const unsigned FULL = 0xffffffffu;

    float acc[8] = {0.f, 0.f, 0.f, 0.f, 0.f, 0.f, 0.f, 0.f};
    acc8_add(acc, __ldg((const uint4*)(g_h1h + (size_t)node * HID) + lane));

    int beg = g_rowstart[node];
    int end = g_rowstart[node + 1];
    for (int i0 = beg; i0 < end; i0 += 32) {
        int cnt = end - i0; if (cnt > 32) cnt = 32;
        int myidx = (i0 + lane < end) ? g_csr[i0 + lane] : 0;
        int j = 0;
        for (; j + 8 <= cnt; j += 8) {
            int nb[8];
#pragma unroll
            for (int u = 0; u < 8; u++) nb[u] = __shfl_sync(FULL, myidx, j + u);
            uint4 v[8];
#pragma unroll
            for (int u = 0; u < 8; u++)
                v[u] = __ldg((const uint4*)(g_h1h + (size_t)nb[u] * HID) + lane);
#pragma unroll
            for (int u = 0; u < 8; u++) acc8_add(acc, v[u]);
        }
        for (; j < cnt; j++) {
            int nb = __shfl_sync(FULL, myidx, j);
            acc8_add(acc, __ldg((const uint4*)(g_h1h + (size_t)nb * HID) + lane));
        }
    }

    float di = g_dinv[node];
    float4 b0 = __ldg((const float4*)bias + lane * 2);
    float4 b1v = __ldg((const float4*)bias + lane * 2 + 1);
    float o[8];
    o[0] = fmaxf(acc[0] * di + b0.x, 0.f) * di;
    o[1] = fmaxf(acc[1] * di + b0.y, 0.f) * di;
    o[2] = fmaxf(acc[2] * di + b0.z, 0.f) * di;
    o[3] = fmaxf(acc[3] * di + b0.w, 0.f) * di;
    o[4] = fmaxf(acc[4] * di + b1v.x, 0.f) * di;
    o[5] = fmaxf(acc[5] * di + b1v.y, 0.f) * di;
    o[6] = fmaxf(acc[6] * di + b1v.z, 0.f) * di;
    o[7] = fmaxf(acc[7] * di + b1v.w, 0.f) * di;
    __half2 h0 = __floats2half2_rn(o[0], o[1]);
    __half2 h1 = __floats2half2_rn(o[2], o[3]);
    __half2 h2 = __floats2half2_rn(o[4], o[5]);
    __half2 h3 = __floats2half2_rn(o[6], o[7]);
    uint4 ov;
    ov.x = *(unsigned*)&h0; ov.y = *(unsigned*)&h1;
    ov.z = *(unsigned*)&h2; ov.w = *(unsigned*)&h3;
    *((uint4*)(g_z1h + (size_t)node * HID) + lane) = ov;
}

__global__ __launch_bounds__(256) void k_agg2(const float* __restrict__ bias, int n)
{
    int node = (blockIdx.x * blockDim.x + threadIdx.x) >> 4;
    if (node >= n) return;
    int lane = threadIdx.x & 31;
    int grp  = lane >> 4;
    int l16  = lane & 15;
    unsigned GM = 0xFFFFu << (grp * 16);

    float acc[8] = {0.f, 0.f, 0.f, 0.f, 0.f, 0.f, 0.f, 0.f};
    acc8_add(acc, __ldg((const uint4*)(g_h2h + (size_t)node * OUT_CH) + l16));

    int beg = g_rowstart[node];
    int end = g_rowstart[node + 1];
    for (int i0 = beg; i0 < end; i0 += 16) {
        int cnt = end - i0; if (cnt > 16) cnt = 16;
        int myidx = (i0 + l16 < end) ? g_csr[i0 + l16] : 0;
        int j = 0;
        for (; j + 8 <= cnt; j += 8) {
            int nb[8];
#pragma unroll
            for (int u = 0; u < 8; u++) nb[u] = __shfl_sync(GM, myidx, j + u, 16);
            uint4 v[8];
#pragma unroll
            for (int u = 0; u < 8; u++)
                v[u] = __ldg((const uint4*)(g_h2h + (size_t)nb[u] * OUT_CH) + l16);
#pragma unroll
            for (int u = 0; u < 8; u++) acc8_add(acc, v[u]);
        }
        for (; j < cnt; j++) {
            int nb = __shfl_sync(GM, myidx, j, 16);
            acc8_add(acc, __ldg((const uint4*)(g_h2h + (size_t)nb * OUT_CH) + l16));
        }
    }

    float di = g_dinv[node];
    float4 b0 = __ldg((const float4*)bias + l16 * 2);
    float4 b1v = __ldg((const float4*)bias + l16 * 2 + 1);
    __half2 h0 = __floats2half2_rn(acc[0] * di + b0.x,  acc[1] * di + b0.y);
    __half2 h1 = __floats2half2_rn(acc[2] * di + b0.z,  acc[3] * di + b0.w);
    __half2 h2 = __floats2half2_rn(acc[4] * di + b1v.x, acc[5] * di + b1v.y);
    __half2 h3 = __floats2half2_rn(acc[6] * di + b1v.z, acc[7] * di + b1v.w);
    uint4 ov;
    ov.x = *(unsigned*)&h0; ov.y = *(unsigned*)&h1;
    ov.z = *(unsigned*)&h2; ov.w = *(unsigned*)&h3;
    *((uint4*)(g_z2h + (size_t)node * OUT_CH) + l16) = ov;
}

// ---------------- decoder: 4 edges per 16-lane group (8 per warp) ----------
__global__ __launch_bounds__(256) void k_decode(
    const int* __restrict__ ei, float* __restrict__ out, int E, int n)
{
    int warp = (blockIdx.x * blockDim.x + threadIdx.x) >> 5;
    int lane = threadIdx.x & 31;
    int grp  = lane >> 4;
    int l16  = lane & 15;
    int e0 = warp * 8 + grp * 4;
    if (e0 >= E) return;

    uint4 va[4], vb[4];
    bool ok[4];
#pragma unroll
    for (int u = 0; u < 4; u++) {
        int e = e0 + u;
        bool has = (e < E);
        int s = has ? __ldg(&ei[e]) : 0;
        int d = has ? __ldg(&ei[(size_t)E + e]) : 0;
        ok[u] = has && (unsigned)s < (unsigned)n && (unsigned)d < (unsigned)n;
        va[u] = make_uint4(0, 0, 0, 0);
        vb[u] = make_uint4(0, 0, 0, 0);
        if (ok[u]) {
            va[u] = __ldg((const uint4*)(g_z2h + (size_t)s * OUT_CH) + l16);
            vb[u] = __ldg((const uint4*)(g_z2h + (size_t)d * OUT_CH) + l16);
        }
    }

    float p[4];
#pragma unroll
    for (int u = 0; u < 4; u++) {
        const __half2* pa = (const __half2*)&va[u];
        const __half2* pb = (const __half2*)&vb[u];
        float acc = 0.f;
#pragma unroll
        for (int j = 0; j < 4; j++) {
            float2 a = __half22float2(pa[j]);
            float2 b = __half22float2(pb[j]);
            acc += a.x * b.x + a.y * b.y;
        }
        p[u] = acc;
    }
#pragma unroll
    for (int off = 8; off > 0; off >>= 1) {
#pragma unroll
        for (int u = 0; u < 4; u++)
            p[u] += __shfl_down_sync(0xffffffffu, p[u], off, 16);
    }
    if (l16 == 0) {
#pragma unroll
        for (int u = 0; u < 4; u++)
            if (e0 + u < E) out[e0 + u] = p[u];
    }
}

// ---------------- launch ---------------------------------------------------
extern "C" void kernel_launch(void* const* d_in, const int* in_sizes, int n_in,
                              void* d_out, int out_size)
{
    const float* x  = (const float*)d_in[0];
    const int*   ei = (const int*)d_in[1];   // [2, E] indices, staged as int32
    const float* W1 = (const float*)d_in[2];
    const float* b1 = (const float*)d_in[3];
    const float* W2 = (const float*)d_in[4];
    const float* b2 = (const float*)d_in[5];
    float* out = (float*)d_out;

    int n = in_sizes[0] / IN_CH;    // 50000
    int E = in_sizes[1] / 2;        // 1600000
    int nh = ((n / 2 + BM - 1) / BM) * BM;   // agg/gemm2 chunk split
    if (nh > n) nh = n;
    int g1h = nh;                            // gemm1/scale chunk split (same)
    int nb = (n + 255) / 256;
    int total4 = n * (IN_CH / 4);
    int half4 = total4 / 2;
    const int CW = (GK * HID + GK * OUT_CH) / 4;   // weight float4 chunks

    cudaStream_t s2;
    cudaStreamCreate(&s2);
    cudaEvent_t evFork, evXa, evG1a, evG1b, evA, evG2a;
    cudaEventCreateWithFlags(&evFork, cudaEventDisableTiming);
    cudaEventCreateWithFlags(&evXa, cudaEventDisableTiming);
    cudaEventCreateWithFlags(&evG1a, cudaEventDisableTiming);
    cudaEventCreateWithFlags(&evG1b, cudaEventDisableTiming);
    cudaEventCreateWithFlags(&evA, cudaEventDisableTiming);
    cudaEventCreateWithFlags(&evG2a, cudaEventDisableTiming);

    cudaEventRecord(evFork, 0);
    cudaStreamWaitEvent(s2, evFork, 0);

    // Branch A (default stream): first half of cvt_x, then CSR build
    k_cvt_x<<<(half4 + 255) / 256, 256>>>(x, 0, half4);
    cudaEventRecord(evXa, 0);
    k_zero_cnt<<<(n + 255) / 256, 256>>>(n);
    k_count8<<<(E / 8 + 255) / 256, 256>>>(ei, E, n);
    k_scan1<<<nb, 256>>>(n);
    k_scan2<<<1, 256>>>(nb, n);
    k_scan3<<<nb, 256>>>(n);
    k_fill8<<<(E / 8 + 255) / 256, 256>>>(ei, E, n);

    // Branch B (s2): rest of cvt (x half + weights, one launch), gemm1 in 2 chunks
    k_cvt_xw<<<((total4 - half4) + CW + 255) / 256, 256, 0, s2>>>(x, half4, total4, W1, W2);
    cudaStreamWaitEvent(s2, evXa, 0);
    {
        dim3 grid(HID / BN, g1h / BM);
        k_gemm1<<<grid, 256, 0, s2>>>(0, n);
    }
    cudaEventRecord(evG1a, s2);
    {
        dim3 grid(HID / BN, (n - g1h + BM - 1) / BM);
        k_gemm1<<<grid, 256, 0, s2>>>(g1h, n);
    }
    cudaEventRecord(evG1b, s2);

    // Default stream (after fill8): scale chunk0 overlaps gemm1 chunk1
    cudaStreamWaitEvent(0, evG1a, 0);
    k_scale_h1<<<(g1h * (HID / 8) + 255) / 256, 256>>>(0, g1h);
    cudaStreamWaitEvent(0, evG1b, 0);
    k_scale_h1<<<((n - g1h) * (HID / 8) + 255) / 256, 256>>>(g1h, n);

    // Pipelined agg1 / gemm2 over two node chunks
    k_agg1<<<(nh * 32 + 255) / 256, 256>>>(b1, 0, nh);           // chunk 0
    cudaEventRecord(evA, 0);

    cudaStreamWaitEvent(s2, evA, 0);                             // gemm2 chunk 0 || agg1 chunk 1
    {
        dim3 grid(OUT_CH / BN, nh / BM);
        k_gemm2<<<grid, 256, 0, s2>>>(0, n);
    }
    cudaEventRecord(evG2a, s2);

    k_agg1<<<((n - nh) * 32 + 255) / 256, 256>>>(b1, nh, n);     // chunk 1
    {
        dim3 grid(OUT_CH / BN, (n - nh + BM - 1) / BM);
        k_gemm2<<<grid, 256>>>(nh, n);
    }
    cudaStreamWaitEvent(0, evG2a, 0);

    // agg2 and decode
    k_agg2<<<(n * 16 + 255) / 256, 256>>>(b2, n);
    k_decode<<<(((E + 7) / 8) * 32 + 255) / 256, 256>>>(ei, out, E, n);

    cudaEventDestroy(evFork);
    cudaEventDestroy(evXa);
    cudaEventDestroy(evG1a);
    cudaEventDestroy(evG1b);
    cudaEventDestroy(evA);
    cudaEventDestroy(evG2a);
    cudaStreamDestroy(s2);
}

// round 16
// speedup vs baseline: 1.3097x; 1.0301x over previous
#include <cuda_runtime.h>
#include <cuda_fp16.h>
#include <mma.h>
#include <cstdint>

using namespace nvcuda;

// Problem constants (GAE: GCN encoder x2 + inner-product decoder)
#define NN 50000
#define NE 1600000
#define IN_CH 256
#define HID 256
#define OUT_CH 128
#define GK 256   // K dim of both GEMMs

// ---------------- scratch (static device globals; no allocation) ----------
__device__ __align__(256) int    g_cnt[NN];
__device__ __align__(256) int    g_rowstart[NN + 1];
__device__ __align__(256) int    g_pos[NN];
__device__ __align__(256) float  g_dinv[NN];
__device__ __align__(256) int    g_csr[NE];
__device__ __align__(256) int    g_blksum[256];
__device__ __align__(256) int    g_blkoff[256];
__device__ __align__(256) __half g_w1h[GK * HID];             // fp16 W1
__device__ __align__(256) __half g_w2h[GK * OUT_CH];          // fp16 W2
__device__ __align__(256) __half g_h1h[(size_t)NN * HID];     // fp16: x@W1, then *= dinv[row]
__device__ __align__(256) __half g_z1h[(size_t)NN * HID];     // fp16: relu(agg*di+b1)*di
__device__ __align__(256) __half g_h2h[(size_t)NN * OUT_CH];  // fp16: z1h@W2
__device__ __align__(256) __half g_z2h[(size_t)NN * OUT_CH];  // fp16: agg*di+b2

// ---------------- degree / CSR build --------------------------------------
__global__ void k_zero_cnt(int n) {
    int i = blockIdx.x * blockDim.x + threadIdx.x;
    if (i < n) g_cnt[i] = 0;
}

// 8 edges per thread via 2x int4 (E is a multiple of 8)
__global__ void k_count8(const int* __restrict__ ei, int E, int n) {
    int i = blockIdx.x * blockDim.x + threadIdx.x;
    if (i < E / 8) {
        int4 d0 = __ldg((const int4*)(ei + E) + 2 * i);
        int4 d1 = __ldg((const int4*)(ei + E) + 2 * i + 1);
        int dd[8] = {d0.x, d0.y, d0.z, d0.w, d1.x, d1.y, d1.z, d1.w};
#pragma unroll
        for (int u = 0; u < 8; u++)
            if ((unsigned)dd[u] < (unsigned)n) atomicAdd(&g_cnt[dd[u]], 1);
    }
}

// multi-block exclusive scan
__global__ void k_scan1(int n) {
    int t = threadIdx.x;
    int i = blockIdx.x * 256 + t;
    int v = (i < n) ? g_cnt[i] : 0;
    __shared__ int sm[256];
    sm[t] = v;
    __syncthreads();
    for (int off = 1; off < 256; off <<= 1) {
        int u = (t >= off) ? sm[t - off] : 0;
        __syncthreads();
        sm[t] += u;
        __syncthreads();
    }
    if (t == 255) g_blksum[blockIdx.x] = sm[255];
}

__global__ void k_scan2(int nb, int n) {
    int t = threadIdx.x;
    int v = (t < nb) ? g_blksum[t] : 0;
    __shared__ int sm[256];
    sm[t] = v;
    __syncthreads();
    for (int off = 1; off < 256; off <<= 1) {
        int u = (t >= off) ? sm[t - off] : 0;
        __syncthreads();
        sm[t] += u;
        __syncthreads();
    }
    if (t < nb) g_blkoff[t] = sm[t] - v;
    if (t == 255) g_rowstart[n] = sm[255];
}

__global__ void k_scan3(int n) {
    int t = threadIdx.x;
    int i = blockIdx.x * 256 + t;
    int v = (i < n) ? g_cnt[i] : 0;
    __shared__ int sm[256];
    sm[t] = v;
    __syncthreads();
    for (int off = 1; off < 256; off <<= 1) {
        int u = (t >= off) ? sm[t - off] : 0;
        __syncthreads();
        sm[t] += u;
        __syncthreads();
    }
    if (i < n) {
        int excl = sm[t] - v + g_blkoff[blockIdx.x];
        g_rowstart[i] = excl;
        g_pos[i] = excl;
        g_dinv[i] = rsqrtf((float)(v + 1));
    }
}

// 8 edges per thread
__global__ void k_fill8(const int* __restrict__ ei, int E, int n) {
    int i = blockIdx.x * blockDim.x + threadIdx.x;
    if (i < E / 8) {
        int4 s0 = __ldg((const int4*)ei + 2 * i);
        int4 s1 = __ldg((const int4*)ei + 2 * i + 1);
        int4 d0 = __ldg((const int4*)(ei + E) + 2 * i);
        int4 d1 = __ldg((const int4*)(ei + E) + 2 * i + 1);
        int ss[8] = {s0.x, s0.y, s0.z, s0.w, s1.x, s1.y, s1.z, s1.w};
        int dd[8] = {d0.x, d0.y, d0.z, d0.w, d1.x, d1.y, d1.z, d1.w};
#pragma unroll
        for (int u = 0; u < 8; u++) {
            if ((unsigned)ss[u] < (unsigned)n && (unsigned)dd[u] < (unsigned)n) {
                int p = atomicAdd(&g_pos[dd[u]], 1);
                if ((unsigned)p < (unsigned)NE) g_csr[p] = ss[u];
            }
        }
    }
}

// ---------------- weight conversion ----------------------------------------
__device__ __forceinline__ void cvt_chunk(const float* __restrict__ S,
                                          __half* __restrict__ D, int i) {
    float4 v = __ldg((const float4*)S + i);
    __half2 lo = __floats2half2_rn(v.x, v.y);
    __half2 hi = __floats2half2_rn(v.z, v.w);
    uint2 o; o.x = *(unsigned*)&lo; o.y = *(unsigned*)&hi;
    *((uint2*)D + i) = o;
}

__global__ void k_cvt_w(const float* __restrict__ W1, const float* __restrict__ W2) {
    int i = blockIdx.x * blockDim.x + threadIdx.x;
    const int C1 = GK * HID / 4;
    const int C2 = GK * OUT_CH / 4;
    if (i < C1) cvt_chunk(W1, g_w1h, i);
    else if (i < C1 + C2) cvt_chunk(W2, g_w2h, i - C1);
}

// h1h[row,:] *= dinv[row] over node range [lo, hi)
__global__ void k_scale_h1(int lo, int hi) {
    int i = lo * (HID / 8) + blockIdx.x * blockDim.x + threadIdx.x;
    if (i >= hi * (HID / 8)) return;
    float di = g_dinv[i / (HID / 8)];
    uint4 v = *((const uint4*)g_h1h + i);
    __half2* p = (__half2*)&v;
#pragma unroll
    for (int j = 0; j < 4; j++) {
        float2 f = __half22float2(p[j]);
        p[j] = __floats2half2_rn(f.x * di, f.y * di);
    }
    *((uint4*)g_h1h + i) = v;
}

// ---------------- GEMM tiles ------------------------------------------------
#define BM 128
#define BN 64
#define BK 32
#define A_LD 40   // BK + 8 pad (halves)
#define B_LD 72   // BN + 8 pad (halves)
#define C_LD 68   // BN + 4 pad (floats)
#define A_BUF (BM * A_LD)
#define B_BUF (BK * B_LD)

// epilogue: stage fp32 accum in smem, convert to fp16, write out
__device__ __forceinline__ void gemm_epilogue(
    float* Cs, __half* __restrict__ C, int row0, int col0, int M, int Ncols,
    wmma::fragment<wmma::accumulator, 16, 16, 16, float> c[2][2],
    int wrow, int wcol, int tid)
{
#pragma unroll
    for (int i = 0; i < 2; i++)
#pragma unroll
        for (int j = 0; j < 2; j++)
            wmma::store_matrix_sync(Cs + (wrow * 32 + i * 16) * C_LD + wcol * 32 + j * 16,
                                    c[i][j], C_LD, wmma::mem_row_major);
    __syncthreads();

    if (tid < BM) {
        int grow = row0 + tid;
        if (grow < M) {
            const float* src = Cs + tid * C_LD;
            __half* dst = C + (size_t)grow * Ncols + col0;
#pragma unroll
            for (int cB = 0; cB < BN; cB += 8) {
                __half2 p0 = __floats2half2_rn(src[cB + 0], src[cB + 1]);
                __half2 p1 = __floats2half2_rn(src[cB + 2], src[cB + 3]);
                __half2 p2 = __floats2half2_rn(src[cB + 4], src[cB + 5]);
                __half2 p3 = __floats2half2_rn(src[cB + 6], src[cB + 7]);
                uint4 o;
                o.x = *(unsigned*)&p0; o.y = *(unsigned*)&p1;
                o.z = *(unsigned*)&p2; o.w = *(unsigned*)&p3;
                *(uint4*)(dst + cB) = o;
            }
        }
    }
}

// GEMM1: A = x in fp32 (converted during smem store), B = W1 fp16.
__global__ __launch_bounds__(256) void k_gemm1(
    const float* __restrict__ A, int rowBase, int M)
{
    const int Ncols = HID;
    __shared__ __align__(16) char sm[BM * C_LD * 4];
    __half* As = (__half*)sm;                      // [2][A_BUF]
    __half* Bs = As + 2 * A_BUF;                   // [2][B_BUF]
    float*  Cs = (float*)sm;

    int tid = threadIdx.x;
    int warp = tid >> 5;
    int wrow = warp >> 1;
    int wcol = warp & 1;
    int row0 = rowBase + blockIdx.y * BM;
    int col0 = blockIdx.x * BN;

    wmma::fragment<wmma::accumulator, 16, 16, 16, float> c[2][2];
#pragma unroll
    for (int i = 0; i < 2; i++)
#pragma unroll
        for (int j = 0; j < 2; j++) wmma::fill_fragment(c[i][j], 0.f);

    // prologue: tile 0 (A fp32: 1024 float4 chunks, 4 per thread)
    {
#pragma unroll
        for (int t = 0; t < 4; t++) {
            int v = tid + t * 256;
            int r = v >> 3;
            int kc = (v & 7) * 4;
            int grow = row0 + r;
            float4 val = make_float4(0.f, 0.f, 0.f, 0.f);
            if (grow < M) val = *(const float4*)(A + (size_t)grow * GK + kc);
            __half2 lo = __floats2half2_rn(val.x, val.y);
            __half2 hi = __floats2half2_rn(val.z, val.w);
            uint2 o; o.x = *(unsigned*)&lo; o.y = *(unsigned*)&hi;
            *(uint2*)(As + r * A_LD + kc) = o;
        }
        int r = tid >> 3;
        int c8 = (tid & 7) * 8;
        uint4 val = *(const uint4*)(g_w1h + (size_t)r * Ncols + col0 + c8);
        *(uint4*)(Bs + r * B_LD + c8) = val;
    }
    __syncthreads();

    for (int k0 = 0; k0 < GK; k0 += BK) {
        int cur = (k0 / BK) & 1;
        int nxt = cur ^ 1;
        bool more = (k0 + BK) < GK;

        float4 pa[4]; uint4 pb;
        if (more) {
#pragma unroll
            for (int t = 0; t < 4; t++) {
                int v = tid + t * 256;
                int r = v >> 3;
                int kc = (v & 7) * 4;
                int grow = row0 + r;
                pa[t] = make_float4(0.f, 0.f, 0.f, 0.f);
                if (grow < M) pa[t] = *(const float4*)(A + (size_t)grow * GK + k0 + BK + kc);
            }
            int r = tid >> 3;
            int c8 = (tid & 7) * 8;
            pb = *(const uint4*)(g_w1h + (size_t)(k0 + BK + r) * Ncols + col0 + c8);
        }

        const __half* Ac = As + cur * A_BUF;
        const __half* Bc = Bs + cur * B_BUF;
#pragma unroll
        for (int kk = 0; kk < BK; kk += 16) {
            wmma::fragment<wmma::matrix_a, 16, 16, 16, __half, wmma::row_major> a[2];
            wmma::fragment<wmma::matrix_b, 16, 16, 16, __half, wmma::row_major> b[2];
#pragma unroll
            for (int i = 0; i < 2; i++)
                wmma::load_matrix_sync(a[i], Ac + (wrow * 32 + i * 16) * A_LD + kk, A_LD);
#pragma unroll
            for (int j = 0; j < 2; j++)
                wmma::load_matrix_sync(b[j], Bc + kk * B_LD + wcol * 32 + j * 16, B_LD);
#pragma unroll
            for (int i = 0; i < 2; i++)
#pragma unroll
                for (int j = 0; j < 2; j++)
                    wmma::mma_sync(c[i][j], a[i], b[j], c[i][j]);
        }

        if (more) {
            __half* An = As + nxt * A_BUF;
            __half* Bn = Bs + nxt * B_BUF;
#pragma unroll
            for (int t = 0; t < 4; t++) {
                int v = tid + t * 256;
                int r = v >> 3;
                int kc = (v & 7) * 4;
                __half2 lo = __floats2half2_rn(pa[t].x, pa[t].y);
                __half2 hi = __floats2half2_rn(pa[t].z, pa[t].w);
                uint2 o; o.x = *(unsigned*)&lo; o.y = *(unsigned*)&hi;
                *(uint2*)(An + r * A_LD + kc) = o;
            }
            int r = tid >> 3;
            int c8 = (tid & 7) * 8;
            *(uint4*)(Bn + r * B_LD + c8) = pb;
        }
        __syncthreads();
    }

    gemm_epilogue(Cs, g_h1h, row0, col0, M, Ncols, c, wrow, wcol, tid);
}

// GEMM2: A = z1h fp16, B = W2 fp16 (double-buffered).
__global__ __launch_bounds__(256) void k_gemm2(int rowBase, int M)
{
    const int Ncols = OUT_CH;
    const __half* __restrict__ A = g_z1h;
    __shared__ __align__(16) char sm[BM * C_LD * 4];
    __half* As = (__half*)sm;
    __half* Bs = As + 2 * A_BUF;
    float*  Cs = (float*)sm;

    int tid = threadIdx.x;
    int warp = tid >> 5;
    int wrow = warp >> 1;
    int wcol = warp & 1;
    int row0 = rowBase + blockIdx.y * BM;
    int col0 = blockIdx.x * BN;

    wmma::fragment<wmma::accumulator, 16, 16, 16, float> c[2][2];
#pragma unroll
    for (int i = 0; i < 2; i++)
#pragma unroll
        for (int j = 0; j < 2; j++) wmma::fill_fragment(c[i][j], 0.f);

    {
#pragma unroll
        for (int t = 0; t < 2; t++) {
            int v = tid + t * 256;
            int r = v >> 2;
            int kc = (v & 3) * 8;
            int grow = row0 + r;
            uint4 val = make_uint4(0u, 0u, 0u, 0u);
            if (grow < M) val = *(const uint4*)(A + (size_t)grow * GK + kc);
            *(uint4*)(As + r * A_LD + kc) = val;
        }
        int r = tid >> 3;
        int c8 = (tid & 7) * 8;
        uint4 val = *(const uint4*)(g_w2h + (size_t)r * Ncols + col0 + c8);
        *(uint4*)(Bs + r * B_LD + c8) = val;
    }
    __syncthreads();

    for (int k0 = 0; k0 < GK; k0 += BK) {
        int cur = (k0 / BK) & 1;
        int nxt = cur ^ 1;
        bool more = (k0 + BK) < GK;

        uint4 pa[2], pb;
        if (more) {
#pragma unroll
            for (int t = 0; t < 2; t++) {
                int v = tid + t * 256;
                int r = v >> 2;
                int kc = (v & 3) * 8;
                int grow = row0 + r;
                pa[t] = make_uint4(0u, 0u, 0u, 0u);
                if (grow < M) pa[t] = *(const uint4*)(A + (size_t)grow * GK + k0 + BK + kc);
            }
            int r = tid >> 3;
            int c8 = (tid & 7) * 8;
            pb = *(const uint4*)(g_w2h + (size_t)(k0 + BK + r) * Ncols + col0 + c8);
        }

        const __half* Ac = As + cur * A_BUF;
        const __half* Bc = Bs + cur * B_BUF;
#pragma unroll
        for (int kk = 0; kk < BK; kk += 16) {
            wmma::fragment<wmma::matrix_a, 16, 16, 16, __half, wmma::row_major> a[2];
            wmma::fragment<wmma::matrix_b, 16, 16, 16, __half, wmma::row_major> b[2];
#pragma unroll
            for (int i = 0; i < 2; i++)
                wmma::load_matrix_sync(a[i], Ac + (wrow * 32 + i * 16) * A_LD + kk, A_LD);
#pragma unroll
            for (int j = 0; j < 2; j++)
                wmma::load_matrix_sync(b[j], Bc + kk * B_LD + wcol * 32 + j * 16, B_LD);
#pragma unroll
            for (int i = 0; i < 2; i++)
#pragma unroll
                for (int j = 0; j < 2; j++)
                    wmma::mma_sync(c[i][j], a[i], b[j], c[i][j]);
        }

        if (more) {
            __half* An = As + nxt * A_BUF;
            __half* Bn = Bs + nxt * B_BUF;
#pragma unroll
            for (int t = 0; t < 2; t++) {
                int v = tid + t * 256;
                int r = v >> 2;
                int kc = (v & 3) * 8;
                *(uint4*)(An + r * A_LD + kc) = pa[t];
            }
            int r = tid >> 3;
            int c8 = (tid & 7) * 8;
            *(uint4*)(Bn + r * B_LD + c8) = pb;
        }
        __syncthreads();
    }

    gemm_epilogue(Cs, g_h2h, row0, col0, M, Ncols, c, wrow, wcol, tid);
}

// ---------------- CSR aggregation (pure row-sum; rows pre-scaled) ----------
__device__ __forceinline__ void acc8_add(float* acc, uint4 v) {
    const __half2* p = (const __half2*)&v;
#pragma unroll
    for (int j = 0; j < 4; j++) {
        float2 f = __half22float2(p[j]);
        acc[2 * j]     += f.x;
        acc[2 * j + 1] += f.y;
    }
}

__global__ __launch_bounds__(256) void k_agg1(const float* __restrict__ bias,
                                              int base, int limit)
{
    int node = base + ((blockIdx.x * blockDim.x + threadIdx.x) >> 5);
    if (node >= limit) return;
    int lane = threadIdx.x & 31;
    const unsigned FULL = 0xffffffffu;

    float acc[8] = {0.f, 0.f, 0.f, 0.f, 0.f, 0.f, 0.f, 0.f};
    acc8_add(acc, __ldg((const uint4*)(g_h1h + (size_t)node * HID) + lane));

    int beg = g_rowstart[node];
    int end = g_rowstart[node + 1];
    for (int i0 = beg; i0 < end; i0 += 32) {
        int cnt = end - i0; if (cnt > 32) cnt = 32;
        int myidx = (i0 + lane < end) ? g_csr[i0 + lane] : 0;
        int j = 0;
        for (; j + 8 <= cnt; j += 8) {
            int nb[8];
#pragma unroll
            for (int u = 0; u < 8; u++) nb[u] = __shfl_sync(FULL, myidx, j + u);
            uint4 v[8];
#pragma unroll
            for (int u = 0; u < 8; u++)
                v[u] = __ldg((const uint4*)(g_h1h + (size_t)nb[u] * HID) + lane);
#pragma unroll
            for (int u = 0; u < 8; u++) acc8_add(acc, v[u]);
        }
        for (; j < cnt; j++) {
            int nb = __shfl_sync(FULL, myidx, j);
            acc8_add(acc, __ldg((const uint4*)(g_h1h + (size_t)nb * HID) + lane));
        }
    }

    float di = g_dinv[node];
    float4 b0 = __ldg((const float4*)bias + lane * 2);
    float4 b1v = __ldg((const float4*)bias + lane * 2 + 1);
    float o[8];
    o[0] = fmaxf(acc[0] * di + b0.x, 0.f) * di;
    o[1] = fmaxf(acc[1] * di + b0.y, 0.f) * di;
    o[2] = fmaxf(acc[2] * di + b0.z, 0.f) * di;
    o[3] = fmaxf(acc[3] * di + b0.w, 0.f) * di;
    o[4] = fmaxf(acc[4] * di + b1v.x, 0.f) * di;
    o[5] = fmaxf(acc[5] * di + b1v.y, 0.f) * di;
    o[6] = fmaxf(acc[6] * di + b1v.z, 0.f) * di;
    o[7] = fmaxf(acc[7] * di + b1v.w, 0.f) * di;
    __half2 h0 = __floats2half2_rn(o[0], o[1]);
    __half2 h1 = __floats2half2_rn(o[2], o[3]);
    __half2 h2 = __floats2half2_rn(o[4], o[5]);
    __half2 h3 = __floats2half2_rn(o[6], o[7]);
    uint4 ov;
    ov.x = *(unsigned*)&h0; ov.y = *(unsigned*)&h1;
    ov.z = *(unsigned*)&h2; ov.w = *(unsigned*)&h3;
    *((uint4*)(g_z1h + (size_t)node * HID) + lane) = ov;
}

__global__ __launch_bounds__(256) void k_agg2(const float* __restrict__ bias, int n)
{
    int node = (blockIdx.x * blockDim.x + threadIdx.x) >> 4;
    if (node >= n) return;
    int lane = threadIdx.x & 31;
    int grp  = lane >> 4;
    int l16  = lane & 15;
    unsigned GM = 0xFFFFu << (grp * 16);

    float acc[8] = {0.f, 0.f, 0.f, 0.f, 0.f, 0.f, 0.f, 0.f};
    acc8_add(acc, __ldg((const uint4*)(g_h2h + (size_t)node * OUT_CH) + l16));

    int beg = g_rowstart[node];
    int end = g_rowstart[node + 1];
    for (int i0 = beg; i0 < end; i0 += 16) {
        int cnt = end - i0; if (cnt > 16) cnt = 16;
        int myidx = (i0 + l16 < end) ? g_csr[i0 + l16] : 0;
        int j = 0;
        for (; j + 8 <= cnt; j += 8) {
            int nb[8];
#pragma unroll
            for (int u = 0; u < 8; u++) nb[u] = __shfl_sync(GM, myidx, j + u, 16);
            uint4 v[8];
#pragma unroll
            for (int u = 0; u < 8; u++)
                v[u] = __ldg((const uint4*)(g_h2h + (size_t)nb[u] * OUT_CH) + l16);
#pragma unroll
            for (int u = 0; u < 8; u++) acc8_add(acc, v[u]);
        }
        for (; j < cnt; j++) {
            int nb = __shfl_sync(GM, myidx, j, 16);
            acc8_add(acc, __ldg((const uint4*)(g_h2h + (size_t)nb * OUT_CH) + l16));
        }
    }

    float di = g_dinv[node];
    float4 b0 = __ldg((const float4*)bias + l16 * 2);
    float4 b1v = __ldg((const float4*)bias + l16 * 2 + 1);
    __half2 h0 = __floats2half2_rn(acc[0] * di + b0.x,  acc[1] * di + b0.y);
    __half2 h1 = __floats2half2_rn(acc[2] * di + b0.z,  acc[3] * di + b0.w);
    __half2 h2 = __floats2half2_rn(acc[4] * di + b1v.x, acc[5] * di + b1v.y);
    __half2 h3 = __floats2half2_rn(acc[6] * di + b1v.z, acc[7] * di + b1v.w);
    uint4 ov;
    ov.x = *(unsigned*)&h0; ov.y = *(unsigned*)&h1;
    ov.z = *(unsigned*)&h2; ov.w = *(unsigned*)&h3;
    *((uint4*)(g_z2h + (size_t)node * OUT_CH) + l16) = ov;
}

// ---------------- decoder: 4 edges per 16-lane group (8 per warp) ----------
__global__ __launch_bounds__(256) void k_decode(
    const int* __restrict__ ei, float* __restrict__ out, int E, int n)
{
    int warp = (blockIdx.x * blockDim.x + threadIdx.x) >> 5;
    int lane = threadIdx.x & 31;
    int grp  = lane >> 4;
    int l16  = lane & 15;
    int e0 = warp * 8 + grp * 4;
    if (e0 >= E) return;

    uint4 va[4], vb[4];
    bool ok[4];
#pragma unroll
    for (int u = 0; u < 4; u++) {
        int e = e0 + u;
        bool has = (e < E);
        int s = has ? __ldg(&ei[e]) : 0;
        int d = has ? __ldg(&ei[(size_t)E + e]) : 0;
        ok[u] = has && (unsigned)s < (unsigned)n && (unsigned)d < (unsigned)n;
        va[u] = make_uint4(0, 0, 0, 0);
        vb[u] = make_uint4(0, 0, 0, 0);
        if (ok[u]) {
            va[u] = __ldg((const uint4*)(g_z2h + (size_t)s * OUT_CH) + l16);
            vb[u] = __ldg((const uint4*)(g_z2h + (size_t)d * OUT_CH) + l16);
        }
    }

    float p[4];
#pragma unroll
    for (int u = 0; u < 4; u++) {
        const __half2* pa = (const __half2*)&va[u];
        const __half2* pb = (const __half2*)&vb[u];
        float acc = 0.f;
#pragma unroll
        for (int j = 0; j < 4; j++) {
            float2 a = __half22float2(pa[j]);
            float2 b = __half22float2(pb[j]);
            acc += a.x * b.x + a.y * b.y;
        }
        p[u] = acc;
    }
#pragma unroll
    for (int off = 8; off > 0; off >>= 1) {
#pragma unroll
        for (int u = 0; u < 4; u++)
            p[u] += __shfl_down_sync(0xffffffffu, p[u], off, 16);
    }
    if (l16 == 0) {
#pragma unroll
        for (int u = 0; u < 4; u++)
            if (e0 + u < E) out[e0 + u] = p[u];
    }
}

// ---------------- launch ---------------------------------------------------
extern "C" void kernel_launch(void* const* d_in, const int* in_sizes, int n_in,
                              void* d_out, int out_size)
{
    const float* x  = (const float*)d_in[0];
    const int*   ei = (const int*)d_in[1];   // [2, E] indices, staged as int32
    const float* W1 = (const float*)d_in[2];
    const float* b1 = (const float*)d_in[3];
    const float* W2 = (const float*)d_in[4];
    const float* b2 = (const float*)d_in[5];
    float* out = (float*)d_out;

    int n = in_sizes[0] / IN_CH;    // 50000
    int E = in_sizes[1] / 2;        // 1600000
    int nb = (n + 255) / 256;
    const int CW = (GK * HID + GK * OUT_CH) / 4;

    // gemm1/scale halves
    int g1h = ((n / 2 + BM - 1) / BM) * BM;
    if (g1h > n) g1h = n;
    // 3-chunk agg1/gemm2 pipeline boundaries (BM-aligned)
    int c1 = ((n / 3 + BM - 1) / BM) * BM;
    int c2 = ((2 * n / 3 + BM - 1) / BM) * BM;
    if (c1 > n) c1 = n;
    if (c2 > n) c2 = n;
    if (c2 < c1) c2 = c1;

    cudaStream_t s2;
    cudaStreamCreate(&s2);
    cudaEvent_t evFork, evG1a, evG1b, evA0, evA1, evG20, evG21;
    cudaEventCreateWithFlags(&evFork, cudaEventDisableTiming);
    cudaEventCreateWithFlags(&evG1a, cudaEventDisableTiming);
    cudaEventCreateWithFlags(&evG1b, cudaEventDisableTiming);
    cudaEventCreateWithFlags(&evA0, cudaEventDisableTiming);
    cudaEventCreateWithFlags(&evA1, cudaEventDisableTiming);
    cudaEventCreateWithFlags(&evG20, cudaEventDisableTiming);
    cudaEventCreateWithFlags(&evG21, cudaEventDisableTiming);

    cudaEventRecord(evFork, 0);
    cudaStreamWaitEvent(s2, evFork, 0);

    // Branch A (default stream): CSR build (atomics / ALU bound)
    k_zero_cnt<<<(n + 255) / 256, 256>>>(n);
    k_count8<<<(E / 8 + 255) / 256, 256>>>(ei, E, n);
    k_scan1<<<nb, 256>>>(n);
    k_scan2<<<1, 256>>>(nb, n);
    k_scan3<<<nb, 256>>>(n);
    k_fill8<<<(E / 8 + 255) / 256, 256>>>(ei, E, n);

    // Branch B (s2): weight cvt, then gemm1 directly from fp32 x (2 chunks)
    k_cvt_w<<<(CW + 255) / 256, 256, 0, s2>>>(W1, W2);
    {
        dim3 grid(HID / BN, g1h / BM);
        k_gemm1<<<grid, 256, 0, s2>>>(x, 0, n);
    }
    cudaEventRecord(evG1a, s2);
    {
        dim3 grid(HID / BN, (n - g1h + BM - 1) / BM);
        k_gemm1<<<grid, 256, 0, s2>>>(x, g1h, n);
    }
    cudaEventRecord(evG1b, s2);

    // Default stream (after fill8, which also guarantees dinv ready):
    // scale chunk0 overlaps gemm1 chunk1
    cudaStreamWaitEvent(0, evG1a, 0);
    k_scale_h1<<<(g1h * (HID / 8) + 255) / 256, 256>>>(0, g1h);
    cudaStreamWaitEvent(0, evG1b, 0);
    k_scale_h1<<<((n - g1h) * (HID / 8) + 255) / 256, 256>>>(g1h, n);

    // 3-chunk pipelined agg1 (default) / gemm2 (s2)
    k_agg1<<<(c1 * 32 + 255) / 256, 256>>>(b1, 0, c1);
    cudaEventRecord(evA0, 0);
    cudaStreamWaitEvent(s2, evA0, 0);
    {
        dim3 grid(OUT_CH / BN, c1 / BM);
        k_gemm2<<<grid, 256, 0, s2>>>(0, n);
    }
    cudaEventRecord(evG20, s2);

    k_agg1<<<((c2 - c1) * 32 + 255) / 256, 256>>>(b1, c1, c2);
    cudaEventRecord(evA1, 0);
    cudaStreamWaitEvent(s2, evA1, 0);
    if (c2 > c1) {
        dim3 grid(OUT_CH / BN, (c2 - c1) / BM);
        k_gemm2<<<grid, 256, 0, s2>>>(c1, n);
    }
    cudaEventRecord(evG21, s2);

    k_agg1<<<((n - c2) * 32 + 255) / 256, 256>>>(b1, c2, n);
    if (n > c2) {
        dim3 grid(OUT_CH / BN, (n - c2 + BM - 1) / BM);
        k_gemm2<<<grid, 256>>>(c2, n);
    }
    cudaStreamWaitEvent(0, evG20, 0);
    cudaStreamWaitEvent(0, evG21, 0);

    // agg2 and decode
    k_agg2<<<(n * 16 + 255) / 256, 256>>>(b2, n);
    k_decode<<<(((E + 7) / 8) * 32 + 255) / 256, 256>>>(ei, out, E, n);

    cudaEventDestroy(evFork);
    cudaEventDestroy(evG1a);
    cudaEventDestroy(evG1b);
    cudaEventDestroy(evA0);
    cudaEventDestroy(evA1);
    cudaEventDestroy(evG20);
    cudaEventDestroy(evG21);
    cudaStreamDestroy(s2);
}

// round 17
// speedup vs baseline: 1.3394x; 1.0227x over previous
#include <cuda_runtime.h>
#include <cuda_fp16.h>
#include <mma.h>
#include <cstdint>

using namespace nvcuda;

// Problem constants (GAE: GCN encoder x2 + inner-product decoder)
#define NN 50000
#define NE 1600000
#define IN_CH 256
#define HID 256
#define OUT_CH 128
#define GK 256   // K dim of both GEMMs

// ---------------- scratch (static device globals; no allocation) ----------
__device__ __align__(256) int    g_cnt[NN];
__device__ __align__(256) int    g_rowstart[NN + 1];
__device__ __align__(256) int    g_pos[NN];
__device__ __align__(256) float  g_dinv[NN];
__device__ __align__(256) int    g_csr[NE];
__device__ __align__(256) int    g_blksum[256];
__device__ __align__(256) int    g_blkoff[256];
__device__ __align__(256) __half g_w1h[GK * HID];             // fp16 W1
__device__ __align__(256) __half g_w2h[GK * OUT_CH];          // fp16 W2
__device__ __align__(256) __half g_h1h[(size_t)NN * HID];     // fp16: x@W1, then *= dinv[row]
__device__ __align__(256) __half g_z1h[(size_t)NN * HID];     // fp16: relu(agg*di+b1)*di
__device__ __align__(256) __half g_h2h[(size_t)NN * OUT_CH];  // fp16: z1h@W2
__device__ __align__(256) __half g_z2h[(size_t)NN * OUT_CH];  // fp16: agg*di+b2

// ---------------- degree / CSR build --------------------------------------
__global__ void k_zero_cnt(int n) {
    int i = blockIdx.x * blockDim.x + threadIdx.x;
    if (i < n) g_cnt[i] = 0;
}

__global__ void k_count8(const int* __restrict__ ei, int E, int n) {
    int i = blockIdx.x * blockDim.x + threadIdx.x;
    if (i < E / 8) {
        int4 d0 = __ldg((const int4*)(ei + E) + 2 * i);
        int4 d1 = __ldg((const int4*)(ei + E) + 2 * i + 1);
        int dd[8] = {d0.x, d0.y, d0.z, d0.w, d1.x, d1.y, d1.z, d1.w};
#pragma unroll
        for (int u = 0; u < 8; u++)
            if ((unsigned)dd[u] < (unsigned)n) atomicAdd(&g_cnt[dd[u]], 1);
    }
}

__global__ void k_scan1(int n) {
    int t = threadIdx.x;
    int i = blockIdx.x * 256 + t;
    int v = (i < n) ? g_cnt[i] : 0;
    __shared__ int sm[256];
    sm[t] = v;
    __syncthreads();
    for (int off = 1; off < 256; off <<= 1) {
        int u = (t >= off) ? sm[t - off] : 0;
        __syncthreads();
        sm[t] += u;
        __syncthreads();
    }
    if (t == 255) g_blksum[blockIdx.x] = sm[255];
}

__global__ void k_scan2(int nb, int n) {
    int t = threadIdx.x;
    int v = (t < nb) ? g_blksum[t] : 0;
    __shared__ int sm[256];
    sm[t] = v;
    __syncthreads();
    for (int off = 1; off < 256; off <<= 1) {
        int u = (t >= off) ? sm[t - off] : 0;
        __syncthreads();
        sm[t] += u;
        __syncthreads();
    }
    if (t < nb) g_blkoff[t] = sm[t] - v;
    if (t == 255) g_rowstart[n] = sm[255];
}

__global__ void k_scan3(int n) {
    int t = threadIdx.x;
    int i = blockIdx.x * 256 + t;
    int v = (i < n) ? g_cnt[i] : 0;
    __shared__ int sm[256];
    sm[t] = v;
    __syncthreads();
    for (int off = 1; off < 256; off <<= 1) {
        int u = (t >= off) ? sm[t - off] : 0;
        __syncthreads();
        sm[t] += u;
        __syncthreads();
    }
    if (i < n) {
        int excl = sm[t] - v + g_blkoff[blockIdx.x];
        g_rowstart[i] = excl;
        g_pos[i] = excl;
        g_dinv[i] = rsqrtf((float)(v + 1));
    }
}

__global__ void k_fill8(const int* __restrict__ ei, int E, int n) {
    int i = blockIdx.x * blockDim.x + threadIdx.x;
    if (i < E / 8) {
        int4 s0 = __ldg((const int4*)ei + 2 * i);
        int4 s1 = __ldg((const int4*)ei + 2 * i + 1);
        int4 d0 = __ldg((const int4*)(ei + E) + 2 * i);
        int4 d1 = __ldg((const int4*)(ei + E) + 2 * i + 1);
        int ss[8] = {s0.x, s0.y, s0.z, s0.w, s1.x, s1.y, s1.z, s1.w};
        int dd[8] = {d0.x, d0.y, d0.z, d0.w, d1.x, d1.y, d1.z, d1.w};
#pragma unroll
        for (int u = 0; u < 8; u++) {
            if ((unsigned)ss[u] < (unsigned)n && (unsigned)dd[u] < (unsigned)n) {
                int p = atomicAdd(&g_pos[dd[u]], 1);
                if ((unsigned)p < (unsigned)NE) g_csr[p] = ss[u];
            }
        }
    }
}

// ---------------- weight conversion ----------------------------------------
__device__ __forceinline__ void cvt_chunk(const float* __restrict__ S,
                                          __half* __restrict__ D, int i) {
    float4 v = __ldg((const float4*)S + i);
    __half2 lo = __floats2half2_rn(v.x, v.y);
    __half2 hi = __floats2half2_rn(v.z, v.w);
    uint2 o; o.x = *(unsigned*)&lo; o.y = *(unsigned*)&hi;
    *((uint2*)D + i) = o;
}

__global__ void k_cvt_w(const float* __restrict__ W1, const float* __restrict__ W2) {
    int i = blockIdx.x * blockDim.x + threadIdx.x;
    const int C1 = GK * HID / 4;
    const int C2 = GK * OUT_CH / 4;
    if (i < C1) cvt_chunk(W1, g_w1h, i);
    else if (i < C1 + C2) cvt_chunk(W2, g_w2h, i - C1);
}

// h1h[row,:] *= dinv[row] over node range [lo, hi)
__global__ void k_scale_h1(int lo, int hi) {
    int i = lo * (HID / 8) + blockIdx.x * blockDim.x + threadIdx.x;
    if (i >= hi * (HID / 8)) return;
    float di = g_dinv[i / (HID / 8)];
    uint4 v = *((const uint4*)g_h1h + i);
    __half2* p = (__half2*)&v;
#pragma unroll
    for (int j = 0; j < 4; j++) {
        float2 f = __half22float2(p[j]);
        p[j] = __floats2half2_rn(f.x * di, f.y * di);
    }
    *((uint4*)g_h1h + i) = v;
}

// ---------------- GEMM tiles ------------------------------------------------
#define BM 128
#define BK 32
#define A_LD 40    // BK + 8 pad (halves)
#define C_LD 68    // 64 + 4 pad (floats)
#define A_BUF (BM * A_LD)       // 5120 halves

// --- GEMM1: BN=128, warp tile 64x32 (8 warps: wrow 0..1, wcol 0..3) --------
#define BN1 128
#define B_LD1 136  // BN1 + 8 pad
#define B_BUF1 (BK * B_LD1)     // 4352 halves

__global__ __launch_bounds__(256) void k_gemm1(
    const float* __restrict__ A, int rowBase, int M)
{
    const int Ncols = HID;
    // tiles: 2*(5120+4352)*2B = 37888 B ; staging union: 128*68*4 = 34816 B
    __shared__ __align__(16) char sm[2 * (A_BUF + B_BUF1) * 2];
    __half* As = (__half*)sm;
    __half* Bs = As + 2 * A_BUF;
    float*  Cs = (float*)sm;

    int tid = threadIdx.x;
    int warp = tid >> 5;
    int wrow = warp >> 2;          // 0..1 -> 64-row band
    int wcol = warp & 3;           // 0..3 -> 32-col band
    int row0 = rowBase + blockIdx.y * BM;
    int col0 = blockIdx.x * BN1;

    wmma::fragment<wmma::accumulator, 16, 16, 16, float> c[4][2];
#pragma unroll
    for (int i = 0; i < 4; i++)
#pragma unroll
        for (int j = 0; j < 2; j++) wmma::fill_fragment(c[i][j], 0.f);

    // prologue: tile 0. A fp32 (1024 float4, 4/thread) convert-on-store; B (512 uint4, 2/thread)
    {
#pragma unroll
        for (int t = 0; t < 4; t++) {
            int v = tid + t * 256;
            int r = v >> 3;
            int kc = (v & 7) * 4;
            int grow = row0 + r;
            float4 val = make_float4(0.f, 0.f, 0.f, 0.f);
            if (grow < M) val = *(const float4*)(A + (size_t)grow * GK + kc);
            __half2 lo = __floats2half2_rn(val.x, val.y);
            __half2 hi = __floats2half2_rn(val.z, val.w);
            uint2 o; o.x = *(unsigned*)&lo; o.y = *(unsigned*)&hi;
            *(uint2*)(As + r * A_LD + kc) = o;
        }
#pragma unroll
        for (int t = 0; t < 2; t++) {
            int v = tid + t * 256;
            int r = v >> 4;                 // 0..31
            int c8 = (v & 15) * 8;          // 0..120
            uint4 val = *(const uint4*)(g_w1h + (size_t)r * Ncols + col0 + c8);
            *(uint4*)(Bs + r * B_LD1 + c8) = val;
        }
    }
    __syncthreads();

    for (int k0 = 0; k0 < GK; k0 += BK) {
        int cur = (k0 / BK) & 1;
        int nxt = cur ^ 1;
        bool more = (k0 + BK) < GK;

        float4 pa[4]; uint4 pb[2];
        if (more) {
#pragma unroll
            for (int t = 0; t < 4; t++) {
                int v = tid + t * 256;
                int r = v >> 3;
                int kc = (v & 7) * 4;
                int grow = row0 + r;
                pa[t] = make_float4(0.f, 0.f, 0.f, 0.f);
                if (grow < M) pa[t] = *(const float4*)(A + (size_t)grow * GK + k0 + BK + kc);
            }
#pragma unroll
            for (int t = 0; t < 2; t++) {
                int v = tid + t * 256;
                int r = v >> 4;
                int c8 = (v & 15) * 8;
                pb[t] = *(const uint4*)(g_w1h + (size_t)(k0 + BK + r) * Ncols + col0 + c8);
            }
        }

        const __half* Ac = As + cur * A_BUF;
        const __half* Bc = Bs + cur * B_BUF1;
#pragma unroll
        for (int kk = 0; kk < BK; kk += 16) {
            wmma::fragment<wmma::matrix_a, 16, 16, 16, __half, wmma::row_major> a[4];
            wmma::fragment<wmma::matrix_b, 16, 16, 16, __half, wmma::row_major> b[2];
#pragma unroll
            for (int i = 0; i < 4; i++)
                wmma::load_matrix_sync(a[i], Ac + (wrow * 64 + i * 16) * A_LD + kk, A_LD);
#pragma unroll
            for (int j = 0; j < 2; j++)
                wmma::load_matrix_sync(b[j], Bc + kk * B_LD1 + wcol * 32 + j * 16, B_LD1);
#pragma unroll
            for (int i = 0; i < 4; i++)
#pragma unroll
                for (int j = 0; j < 2; j++)
                    wmma::mma_sync(c[i][j], a[i], b[j], c[i][j]);
        }

        if (more) {
            __half* An = As + nxt * A_BUF;
            __half* Bn = Bs + nxt * B_BUF1;
#pragma unroll
            for (int t = 0; t < 4; t++) {
                int v = tid + t * 256;
                int r = v >> 3;
                int kc = (v & 7) * 4;
                __half2 lo = __floats2half2_rn(pa[t].x, pa[t].y);
                __half2 hi = __floats2half2_rn(pa[t].z, pa[t].w);
                uint2 o; o.x = *(unsigned*)&lo; o.y = *(unsigned*)&hi;
                *(uint2*)(An + r * A_LD + kc) = o;
            }
#pragma unroll
            for (int t = 0; t < 2; t++) {
                int v = tid + t * 256;
                int r = v >> 4;
                int c8 = (v & 15) * 8;
                *(uint4*)(Bn + r * B_LD1 + c8) = pb[t];
            }
        }
        __syncthreads();
    }

    // epilogue: two 64-column passes through the fp32 staging buffer
#pragma unroll
    for (int pass = 0; pass < 2; pass++) {
        __syncthreads();
        if ((wcol >> 1) == pass) {
#pragma unroll
            for (int i = 0; i < 4; i++)
#pragma unroll
                for (int j = 0; j < 2; j++)
                    wmma::store_matrix_sync(
                        Cs + (wrow * 64 + i * 16) * C_LD + (wcol & 1) * 32 + j * 16,
                        c[i][j], C_LD, wmma::mem_row_major);
        }
        __syncthreads();
        if (tid < BM) {
            int grow = row0 + tid;
            if (grow < M) {
                const float* src = Cs + tid * C_LD;
                __half* dst = g_h1h + (size_t)grow * Ncols + col0 + pass * 64;
#pragma unroll
                for (int cB = 0; cB < 64; cB += 8) {
                    __half2 p0 = __floats2half2_rn(src[cB + 0], src[cB + 1]);
                    __half2 p1 = __floats2half2_rn(src[cB + 2], src[cB + 3]);
                    __half2 p2 = __floats2half2_rn(src[cB + 4], src[cB + 5]);
                    __half2 p3 = __floats2half2_rn(src[cB + 6], src[cB + 7]);
                    uint4 o;
                    o.x = *(unsigned*)&p0; o.y = *(unsigned*)&p1;
                    o.z = *(unsigned*)&p2; o.w = *(unsigned*)&p3;
                    *(uint4*)(dst + cB) = o;
                }
            }
        }
    }
}

// --- GEMM2: BN=64, warp tile 32x32 (unchanged from round 16) ---------------
#define BN 64
#define B_LD 72
#define B_BUF (BK * B_LD)

__global__ __launch_bounds__(256) void k_gemm2(int rowBase, int M)
{
    const int Ncols = OUT_CH;
    const __half* __restrict__ A = g_z1h;
    __shared__ __align__(16) char sm[BM * C_LD * 4];
    __half* As = (__half*)sm;
    __half* Bs = As + 2 * A_BUF;
    float*  Cs = (float*)sm;

    int tid = threadIdx.x;
    int warp = tid >> 5;
    int wrow = warp >> 1;
    int wcol = warp & 1;
    int row0 = rowBase + blockIdx.y * BM;
    int col0 = blockIdx.x * BN;

    wmma::fragment<wmma::accumulator, 16, 16, 16, float> c[2][2];
#pragma unroll
    for (int i = 0; i < 2; i++)
#pragma unroll
        for (int j = 0; j < 2; j++) wmma::fill_fragment(c[i][j], 0.f);

    {
#pragma unroll
        for (int t = 0; t < 2; t++) {
            int v = tid + t * 256;
            int r = v >> 2;
            int kc = (v & 3) * 8;
            int grow = row0 + r;
            uint4 val = make_uint4(0u, 0u, 0u, 0u);
            if (grow < M) val = *(const uint4*)(A + (size_t)grow * GK + kc);
            *(uint4*)(As + r * A_LD + kc) = val;
        }
        int r = tid >> 3;
        int c8 = (tid & 7) * 8;
        uint4 val = *(const uint4*)(g_w2h + (size_t)r * Ncols + col0 + c8);
        *(uint4*)(Bs + r * B_LD + c8) = val;
    }
    __syncthreads();

    for (int k0 = 0; k0 < GK; k0 += BK) {
        int cur = (k0 / BK) & 1;
        int nxt = cur ^ 1;
        bool more = (k0 + BK) < GK;

        uint4 pa[2], pb;
        if (more) {
#pragma unroll
            for (int t = 0; t < 2; t++) {
                int v = tid + t * 256;
                int r = v >> 2;
                int kc = (v & 3) * 8;
                int grow = row0 + r;
                pa[t] = make_uint4(0u, 0u, 0u, 0u);
                if (grow < M) pa[t] = *(const uint4*)(A + (size_t)grow * GK + k0 + BK + kc);
            }
            int r = tid >> 3;
            int c8 = (tid & 7) * 8;
            pb = *(const uint4*)(g_w2h + (size_t)(k0 + BK + r) * Ncols + col0 + c8);
        }

        const __half* Ac = As + cur * A_BUF;
        const __half* Bc = Bs + cur * B_BUF;
#pragma unroll
        for (int kk = 0; kk < BK; kk += 16) {
            wmma::fragment<wmma::matrix_a, 16, 16, 16, __half, wmma::row_major> a[2];
            wmma::fragment<wmma::matrix_b, 16, 16, 16, __half, wmma::row_major> b[2];
#pragma unroll
            for (int i = 0; i < 2; i++)
                wmma::load_matrix_sync(a[i], Ac + (wrow * 32 + i * 16) * A_LD + kk, A_LD);
#pragma unroll
            for (int j = 0; j < 2; j++)
                wmma::load_matrix_sync(b[j], Bc + kk * B_LD + wcol * 32 + j * 16, B_LD);
#pragma unroll
            for (int i = 0; i < 2; i++)
#pragma unroll
                for (int j = 0; j < 2; j++)
                    wmma::mma_sync(c[i][j], a[i], b[j], c[i][j]);
        }

        if (more) {
            __half* An = As + nxt * A_BUF;
            __half* Bn = Bs + nxt * B_BUF;
#pragma unroll
            for (int t = 0; t < 2; t++) {
                int v = tid + t * 256;
                int r = v >> 2;
                int kc = (v & 3) * 8;
                *(uint4*)(An + r * A_LD + kc) = pa[t];
            }
            int r = tid >> 3;
            int c8 = (tid & 7) * 8;
            *(uint4*)(Bn + r * B_LD + c8) = pb;
        }
        __syncthreads();
    }

#pragma unroll
    for (int i = 0; i < 2; i++)
#pragma unroll
        for (int j = 0; j < 2; j++)
            wmma::store_matrix_sync(Cs + (wrow * 32 + i * 16) * C_LD + wcol * 32 + j * 16,
                                    c[i][j], C_LD, wmma::mem_row_major);
    __syncthreads();

    if (tid < BM) {
        int grow = row0 + tid;
        if (grow < M) {
            const float* src = Cs + tid * C_LD;
            __half* dst = g_h2h + (size_t)grow * Ncols + col0;
#pragma unroll
            for (int cB = 0; cB < BN; cB += 8) {
                __half2 p0 = __floats2half2_rn(src[cB + 0], src[cB + 1]);
                __half2 p1 = __floats2half2_rn(src[cB + 2], src[cB + 3]);
                __half2 p2 = __floats2half2_rn(src[cB + 4], src[cB + 5]);
                __half2 p3 = __floats2half2_rn(src[cB + 6], src[cB + 7]);
                uint4 o;
                o.x = *(unsigned*)&p0; o.y = *(unsigned*)&p1;
                o.z = *(unsigned*)&p2; o.w = *(unsigned*)&p3;
                *(uint4*)(dst + cB) = o;
            }
        }
    }
}

// ---------------- CSR aggregation (pure row-sum; rows pre-scaled) ----------
__device__ __forceinline__ void acc8_add(float* acc, uint4 v) {
    const __half2* p = (const __half2*)&v;
#pragma unroll
    for (int j = 0; j < 4; j++) {
        float2 f = __half22float2(p[j]);
        acc[2 * j]     += f.x;
        acc[2 * j + 1] += f.y;
    }
}

__global__ __launch_bounds__(256) void k_agg1(const float* __restrict__ bias,
                                              int base, int limit)
{
    int node = base + ((blockIdx.x * blockDim.x + threadIdx.x) >> 5);
    if (node >= limit) return;
    int lane = threadIdx.x & 31;
    const unsigned FULL = 0xffffffffu;

    float acc[8] = {0.f, 0.f, 0.f, 0.f, 0.f, 0.f, 0.f, 0.f};
    acc8_add(acc, __ldg((const uint4*)(g_h1h + (size_t)node * HID) + lane));

    int beg = g_rowstart[node];
    int end = g_rowstart[node + 1];
    for (int i0 = beg; i0 < end; i0 += 32) {
        int cnt = end - i0; if (cnt > 32) cnt = 32;
        int myidx = (i0 + lane < end) ? g_csr[i0 + lane] : 0;
        int j = 0;
        for (; j + 8 <= cnt; j += 8) {
            int nb[8];
#pragma unroll
            for (int u = 0; u < 8; u++) nb[u] = __shfl_sync(FULL, myidx, j + u);
            uint4 v[8];
#pragma unroll
            for (int u = 0; u < 8; u++)
                v[u] = __ldg((const uint4*)(g_h1h + (size_t)nb[u] * HID) + lane);
#pragma unroll
            for (int u = 0; u < 8; u++) acc8_add(acc, v[u]);
        }
        for (; j < cnt; j++) {
            int nb = __shfl_sync(FULL, myidx, j);
            acc8_add(acc, __ldg((const uint4*)(g_h1h + (size_t)nb * HID) + lane));
        }
    }

    float di = g_dinv[node];
    float4 b0 = __ldg((const float4*)bias + lane * 2);
    float4 b1v = __ldg((const float4*)bias + lane * 2 + 1);
    float o[8];
    o[0] = fmaxf(acc[0] * di + b0.x, 0.f) * di;
    o[1] = fmaxf(acc[1] * di + b0.y, 0.f) * di;
    o[2] = fmaxf(acc[2] * di + b0.z, 0.f) * di;
    o[3] = fmaxf(acc[3] * di + b0.w, 0.f) * di;
    o[4] = fmaxf(acc[4] * di + b1v.x, 0.f) * di;
    o[5] = fmaxf(acc[5] * di + b1v.y, 0.f) * di;
    o[6] = fmaxf(acc[6] * di + b1v.z, 0.f) * di;
    o[7] = fmaxf(acc[7] * di + b1v.w, 0.f) * di;
    __half2 h0 = __floats2half2_rn(o[0], o[1]);
    __half2 h1 = __floats2half2_rn(o[2], o[3]);
    __half2 h2 = __floats2half2_rn(o[4], o[5]);
    __half2 h3 = __floats2half2_rn(o[6], o[7]);
    uint4 ov;
    ov.x = *(unsigned*)&h0; ov.y = *(unsigned*)&h1;
    ov.z = *(unsigned*)&h2; ov.w = *(unsigned*)&h3;
    *((uint4*)(g_z1h + (size_t)node * HID) + lane) = ov;
}

__global__ __launch_bounds__(256) void k_agg2(const float* __restrict__ bias, int n)
{
    int node = (blockIdx.x * blockDim.x + threadIdx.x) >> 4;
    if (node >= n) return;
    int lane = threadIdx.x & 31;
    int grp  = lane >> 4;
    int l16  = lane & 15;
    unsigned GM = 0xFFFFu << (grp * 16);

    float acc[8] = {0.f, 0.f, 0.f, 0.f, 0.f, 0.f, 0.f, 0.f};
    acc8_add(acc, __ldg((const uint4*)(g_h2h + (size_t)node * OUT_CH) + l16));

    int beg = g_rowstart[node];
    int end = g_rowstart[node + 1];
    for (int i0 = beg; i0 < end; i0 += 16) {
        int cnt = end - i0; if (cnt > 16) cnt = 16;
        int myidx = (i0 + l16 < end) ? g_csr[i0 + l16] : 0;
        int j = 0;
        for (; j + 8 <= cnt; j += 8) {
            int nb[8];
#pragma unroll
            for (int u = 0; u < 8; u++) nb[u] = __shfl_sync(GM, myidx, j + u, 16);
            uint4 v[8];
#pragma unroll
            for (int u = 0; u < 8; u++)
                v[u] = __ldg((const uint4*)(g_h2h + (size_t)nb[u] * OUT_CH) + l16);
#pragma unroll
            for (int u = 0; u < 8; u++) acc8_add(acc, v[u]);
        }
        for (; j < cnt; j++) {
            int nb = __shfl_sync(GM, myidx, j, 16);
            acc8_add(acc, __ldg((const uint4*)(g_h2h + (size_t)nb * OUT_CH) + l16));
        }
    }

    float di = g_dinv[node];
    float4 b0 = __ldg((const float4*)bias + l16 * 2);
    float4 b1v = __ldg((const float4*)bias + l16 * 2 + 1);
    __half2 h0 = __floats2half2_rn(acc[0] * di + b0.x,  acc[1] * di + b0.y);
    __half2 h1 = __floats2half2_rn(acc[2] * di + b0.z,  acc[3] * di + b0.w);
    __half2 h2 = __floats2half2_rn(acc[4] * di + b1v.x, acc[5] * di + b1v.y);
    __half2 h3 = __floats2half2_rn(acc[6] * di + b1v.z, acc[7] * di + b1v.w);
    uint4 ov;
    ov.x = *(unsigned*)&h0; ov.y = *(unsigned*)&h1;
    ov.z = *(unsigned*)&h2; ov.w = *(unsigned*)&h3;
    *((uint4*)(g_z2h + (size_t)node * OUT_CH) + l16) = ov;
}

// ---------------- decoder: 4 edges per 16-lane group (8 per warp) ----------
__global__ __launch_bounds__(256) void k_decode(
    const int* __restrict__ ei, float* __restrict__ out, int E, int n)
{
    int warp = (blockIdx.x * blockDim.x + threadIdx.x) >> 5;
    int lane = threadIdx.x & 31;
    int grp  = lane >> 4;
    int l16  = lane & 15;
    int e0 = warp * 8 + grp * 4;
    if (e0 >= E) return;

    uint4 va[4], vb[4];
    bool ok[4];
#pragma unroll
    for (int u = 0; u < 4; u++) {
        int e = e0 + u;
        bool has = (e < E);
        int s = has ? __ldg(&ei[e]) : 0;
        int d = has ? __ldg(&ei[(size_t)E + e]) : 0;
        ok[u] = has && (unsigned)s < (unsigned)n && (unsigned)d < (unsigned)n;
        va[u] = make_uint4(0, 0, 0, 0);
        vb[u] = make_uint4(0, 0, 0, 0);
        if (ok[u]) {
            va[u] = __ldg((const uint4*)(g_z2h + (size_t)s * OUT_CH) + l16);
            vb[u] = __ldg((const uint4*)(g_z2h + (size_t)d * OUT_CH) + l16);
        }
    }

    float p[4];
#pragma unroll
    for (int u = 0; u < 4; u++) {
        const __half2* pa = (const __half2*)&va[u];
        const __half2* pb = (const __half2*)&vb[u];
        float acc = 0.f;
#pragma unroll
        for (int j = 0; j < 4; j++) {
            float2 a = __half22float2(pa[j]);
            float2 b = __half22float2(pb[j]);
            acc += a.x * b.x + a.y * b.y;
        }
        p[u] = acc;
    }
#pragma unroll
    for (int off = 8; off > 0; off >>= 1) {
#pragma unroll
        for (int u = 0; u < 4; u++)
            p[u] += __shfl_down_sync(0xffffffffu, p[u], off, 16);
    }
    if (l16 == 0) {
#pragma unroll
        for (int u = 0; u < 4; u++)
            if (e0 + u < E) out[e0 + u] = p[u];
    }
}

// ---------------- launch ---------------------------------------------------
extern "C" void kernel_launch(void* const* d_in, const int* in_sizes, int n_in,
                              void* d_out, int out_size)
{
    const float* x  = (const float*)d_in[0];
    const int*   ei = (const int*)d_in[1];   // [2, E] indices, staged as int32
    const float* W1 = (const float*)d_in[2];
    const float* b1 = (const float*)d_in[3];
    const float* W2 = (const float*)d_in[4];
    const float* b2 = (const float*)d_in[5];
    float* out = (float*)d_out;

    int n = in_sizes[0] / IN_CH;    // 50000
    int E = in_sizes[1] / 2;        // 1600000
    int nb = (n + 255) / 256;
    const int CW = (GK * HID + GK * OUT_CH) / 4;

    int g1h = ((n / 2 + BM - 1) / BM) * BM;
    if (g1h > n) g1h = n;
    int c1 = ((n / 3 + BM - 1) / BM) * BM;
    int c2 = ((2 * n / 3 + BM - 1) / BM) * BM;
    if (c1 > n) c1 = n;
    if (c2 > n) c2 = n;
    if (c2 < c1) c2 = c1;

    cudaStream_t s2;
    cudaStreamCreate(&s2);
    cudaEvent_t evFork, evG1a, evG1b, evA0, evA1, evG20, evG21;
    cudaEventCreateWithFlags(&evFork, cudaEventDisableTiming);
    cudaEventCreateWithFlags(&evG1a, cudaEventDisableTiming);
    cudaEventCreateWithFlags(&evG1b, cudaEventDisableTiming);
    cudaEventCreateWithFlags(&evA0, cudaEventDisableTiming);
    cudaEventCreateWithFlags(&evA1, cudaEventDisableTiming);
    cudaEventCreateWithFlags(&evG20, cudaEventDisableTiming);
    cudaEventCreateWithFlags(&evG21, cudaEventDisableTiming);

    cudaEventRecord(evFork, 0);
    cudaStreamWaitEvent(s2, evFork, 0);

    // Branch A (default stream): CSR build (atomics / ALU bound)
    k_zero_cnt<<<(n + 255) / 256, 256>>>(n);
    k_count8<<<(E / 8 + 255) / 256, 256>>>(ei, E, n);
    k_scan1<<<nb, 256>>>(n);
    k_scan2<<<1, 256>>>(nb, n);
    k_scan3<<<nb, 256>>>(n);
    k_fill8<<<(E / 8 + 255) / 256, 256>>>(ei, E, n);

    // Branch B (s2): weight cvt, then gemm1 (BN=128) in 2 row chunks
    k_cvt_w<<<(CW + 255) / 256, 256, 0, s2>>>(W1, W2);
    {
        dim3 grid(HID / BN1, g1h / BM);
        k_gemm1<<<grid, 256, 0, s2>>>(x, 0, n);
    }
    cudaEventRecord(evG1a, s2);
    {
        dim3 grid(HID / BN1, (n - g1h + BM - 1) / BM);
        k_gemm1<<<grid, 256, 0, s2>>>(x, g1h, n);
    }
    cudaEventRecord(evG1b, s2);

    // Default stream: scale chunk0 overlaps gemm1 chunk1
    cudaStreamWaitEvent(0, evG1a, 0);
    k_scale_h1<<<(g1h * (HID / 8) + 255) / 256, 256>>>(0, g1h);
    cudaStreamWaitEvent(0, evG1b, 0);
    k_scale_h1<<<((n - g1h) * (HID / 8) + 255) / 256, 256>>>(g1h, n);

    // 3-chunk pipelined agg1 (default) / gemm2 (s2)
    k_agg1<<<(c1 * 32 + 255) / 256, 256>>>(b1, 0, c1);
    cudaEventRecord(evA0, 0);
    cudaStreamWaitEvent(s2, evA0, 0);
    {
        dim3 grid(OUT_CH / BN, c1 / BM);
        k_gemm2<<<grid, 256, 0, s2>>>(0, n);
    }
    cudaEventRecord(evG20, s2);

    k_agg1<<<((c2 - c1) * 32 + 255) / 256, 256>>>(b1, c1, c2);
    cudaEventRecord(evA1, 0);
    cudaStreamWaitEvent(s2, evA1, 0);
    if (c2 > c1) {
        dim3 grid(OUT_CH / BN, (c2 - c1) / BM);
        k_gemm2<<<grid, 256, 0, s2>>>(c1, n);
    }
    cudaEventRecord(evG21, s2);

    k_agg1<<<((n - c2) * 32 + 255) / 256, 256>>>(b1, c2, n);
    if (n > c2) {
        dim3 grid(OUT_CH / BN, (n - c2 + BM - 1) / BM);
        k_gemm2<<<grid, 256>>>(c2, n);
    }
    cudaStreamWaitEvent(0, evG20, 0);
    cudaStreamWaitEvent(0, evG21, 0);

    // agg2 and decode
    k_agg2<<<(n * 16 + 255) / 256, 256>>>(b2, n);
    k_decode<<<(((E + 7) / 8) * 32 + 255) / 256, 256>>>(ei, out, E, n);

    cudaEventDestroy(evFork);
    cudaEventDestroy(evG1a);
    cudaEventDestroy(evG1b);
    cudaEventDestroy(evA0);
    cudaEventDestroy(evA1);
    cudaEventDestroy(evG20);
    cudaEventDestroy(evG21);
    cudaStreamDestroy(s2);
}